// round 7
// baseline (speedup 1.0000x reference)
#include <cuda_runtime.h>
#include <math.h>
#include <stdint.h>

#define L 512
#define B 32
#define D 256
#define H 256
#define G 768           // 3*H
#define LB (L*B)        // 16384

// ---------------- scratch (static device globals; no allocation) ----------------
__device__ float g_tp[LB*H];            // tanh(Wp  v)     [i,b,h]
__device__ float g_tq[LB*H];            // tanh(Wp_ v)     [l,b,h]
__device__ float g_c [LB*D];            // context         [i,b,d]
__device__ float g_gi[LB*G];            // W_ih c + b_ih   [i,b,3H]

// ---------------- helpers ----------------
__device__ __forceinline__ float frcp_approx(float x) {
    float r;
    asm("rcp.approx.f32 %0, %1;" : "=f"(r) : "f"(x));
    return r;
}
__device__ __forceinline__ float fex2(float x) {   // 2^x via MUFU
    float r;
    asm("ex2.approx.f32 %0, %1;" : "=f"(r) : "f"(x));
    return r;
}

__device__ __forceinline__ uint32_t smem_u32(const void* p) {
    uint32_t a;
    asm("{ .reg .u64 t; cvta.to.shared.u64 t, %1; cvt.u32.u64 %0, t; }" : "=r"(a) : "l"(p));
    return a;
}

__device__ __forceinline__ void st_shared_cluster_f32(uint32_t laddr, uint32_t rank, float v) {
    asm volatile(
        "{ .reg .b32 ra; mapa.shared::cluster.u32 ra, %0, %1; st.shared::cluster.f32 [ra], %2; }"
        :: "r"(laddr), "r"(rank), "f"(v) : "memory");
}

__device__ __forceinline__ void cluster_sync_all() {
    asm volatile("barrier.cluster.arrive.aligned;" ::: "memory");
    asm volatile("barrier.cluster.wait.aligned;" ::: "memory");
}

#define KLOG2E 1.4426950408889634f

// strides chosen for vector alignment:
//  TP stride 68 (mult of 4 -> float4-aligned; 68 mod 32 = 4 banks offset per h)
//  TQ stride 34 (mult of 2 -> float2-aligned)
//  Ssm stride 33 (scalar access only)
#define TP_STRIDE 68
#define TQ_STRIDE 34

// ---------------- 1) projection GEMM + tanh epilogue (T only) ----------------
// T[n,h] = tanh( sum_d X[n,d] * W[h,d] )
__global__ __launch_bounds__(256) void proj_kernel(
    const float* __restrict__ X, const float* __restrict__ W,
    float* __restrict__ T)
{
    __shared__ float Xs[64][33];
    __shared__ float Ws[64][33];
    int n0 = blockIdx.x * 64, h0 = blockIdx.y * 64;
    int t = threadIdx.x;
    int ti = t >> 4, tl = t & 15;
    float acc[4][4] = {};

    for (int k0 = 0; k0 < 256; k0 += 32) {
        #pragma unroll
        for (int it = 0; it < 8; ++it) {
            int idx = t + it * 256;
            int r = idx >> 5, kk = idx & 31;
            Xs[r][kk] = X[(n0 + r) * 256 + k0 + kk];
            Ws[r][kk] = W[(h0 + r) * 256 + k0 + kk];
        }
        __syncthreads();
        #pragma unroll
        for (int kk = 0; kk < 32; ++kk) {
            float a[4], bb[4];
            #pragma unroll
            for (int i = 0; i < 4; ++i) a[i] = Xs[ti * 4 + i][kk];
            #pragma unroll
            for (int j = 0; j < 4; ++j) bb[j] = Ws[tl + 16 * j][kk];
            #pragma unroll
            for (int i = 0; i < 4; ++i)
                #pragma unroll
                for (int j = 0; j < 4; ++j)
                    acc[i][j] = fmaf(a[i], bb[j], acc[i][j]);
        }
        __syncthreads();
    }
    #pragma unroll
    for (int i = 0; i < 4; ++i) {
        int n = n0 + ti * 4 + i;
        #pragma unroll
        for (int j = 0; j < 4; ++j) {
            int h = h0 + tl + 16 * j;
            T[n * 256 + h] = tanhf(acc[i][j]);
        }
    }
}

// ---------------- 2) fused attention: scores + online softmax + context ----------------
// Per CTA: (i-tile of 64, one batch b). For each l-chunk of 32:
//   S[i][l] = sum_h V[b,h] * (tp[i,h]+tq[l,h]) / (1 + tp[i,h]*tq[l,h])
//   online softmax over l, context c[i][d] += P[i][l] * v[l,b,d] (v from L2)
#define ATTN_SMEM_FLOATS (256*TP_STRIDE + 256*TQ_STRIDE + 64*33 + 256 + 64 + 64)
#define ATTN_SMEM_BYTES  (ATTN_SMEM_FLOATS * 4)

__global__ __launch_bounds__(256) void attn_kernel(const float* __restrict__ v,
                                                   const float* __restrict__ Vv)
{
    extern __shared__ float sm[];
    float* TP   = sm;                          // [h][TP_STRIDE] transposed tp tile
    float* TQ   = TP + 256*TP_STRIDE;          // [h][TQ_STRIDE] transposed tq chunk
    float* Ssm  = TQ + 256*TQ_STRIDE;          // [64][33] scores -> probabilities
    float* Vs   = Ssm + 64*33;                 // [256] V[b,:]
    float* CORR = Vs + 256;                    // [64] per-row rescale factor
    float* RS   = CORR + 64;                   // [64] final row sums

    int b   = blockIdx.y;
    int i0  = blockIdx.x * 64;
    int tid = threadIdx.x;
    int ti  = tid >> 4, tl = tid & 15;

    for (int h = tid; h < 256; h += 256) Vs[h] = Vv[b * 256 + h];

    // stage tp tile transposed: TP[h][i]
    {
        int i = tid >> 2, q = tid & 3;
        const float* src = g_tp + ((size_t)(i0 + i) * 32 + b) * 256;
        #pragma unroll
        for (int pass = 0; pass < 16; ++pass) {
            int h = pass * 16 + q * 4;
            float4 t4 = *(const float4*)(src + h);
            TP[(h + 0) * TP_STRIDE + i] = t4.x;
            TP[(h + 1) * TP_STRIDE + i] = t4.y;
            TP[(h + 2) * TP_STRIDE + i] = t4.z;
            TP[(h + 3) * TP_STRIDE + i] = t4.w;
        }
    }

    float m = -1e30f, s = 0.f;  // per-row online stats (valid for tid < 64, row = tid)
    float c[4][16];
    #pragma unroll
    for (int a = 0; a < 4; ++a)
        #pragma unroll
        for (int j = 0; j < 16; ++j) c[a][j] = 0.f;

    __syncthreads();

    for (int l0 = 0; l0 < 512; l0 += 32) {
        // stage tq chunk transposed: TQ[h][l]
        {
            int l = tid >> 3, q = tid & 7;
            const float* src = g_tq + ((size_t)(l0 + l) * 32 + b) * 256;
            #pragma unroll
            for (int pass = 0; pass < 8; ++pass) {
                int h = pass * 32 + q * 4;
                float4 t4 = *(const float4*)(src + h);
                TQ[(h + 0) * TQ_STRIDE + l] = t4.x;
                TQ[(h + 1) * TQ_STRIDE + l] = t4.y;
                TQ[(h + 2) * TQ_STRIDE + l] = t4.z;
                TQ[(h + 3) * TQ_STRIDE + l] = t4.w;
            }
        }
        __syncthreads();

        // scores: 4(i) x 2(l) microtile over 256 h
        float acc[4][2] = {};
        const float* tpp = TP + ti * 4;       // float4-aligned: h*68 + ti*4 ≡ 0 (mod 4)
        const float* tqp = TQ + tl * 2;       // float2-aligned: h*34 + tl*2 ≡ 0 (mod 2)
        #pragma unroll 4
        for (int h = 0; h < 256; ++h) {
            float4 tp4 = *(const float4*)(tpp + h * TP_STRIDE);
            float2 tq2 = *(const float2*)(tqp + h * TQ_STRIDE);
            float vh = Vs[h];
            float tpv[4] = {tp4.x, tp4.y, tp4.z, tp4.w};
            #pragma unroll
            for (int a = 0; a < 4; ++a) {
                float s0 = tpv[a] + tq2.x;
                float s1 = tpv[a] + tq2.y;
                float d0 = fmaf(tpv[a], tq2.x, 1.0f);
                float d1 = fmaf(tpv[a], tq2.y, 1.0f);
                acc[a][0] = fmaf(vh * s0, frcp_approx(d0), acc[a][0]);
                acc[a][1] = fmaf(vh * s1, frcp_approx(d1), acc[a][1]);
            }
        }
        #pragma unroll
        for (int a = 0; a < 4; ++a) {
            Ssm[(ti * 4 + a) * 33 + tl * 2 + 0] = acc[a][0];
            Ssm[(ti * 4 + a) * 33 + tl * 2 + 1] = acc[a][1];
        }
        __syncthreads();

        // online softmax on 64 rows (one per thread, tid < 64)
        if (tid < 64) {
            float* Sr = Ssm + tid * 33;
            float mc = Sr[0];
            #pragma unroll
            for (int l = 1; l < 32; ++l) mc = fmaxf(mc, Sr[l]);
            float m2 = fmaxf(m, mc);
            float cr = fex2((m - m2) * KLOG2E);    // exp(m - m2); ~0 on first chunk
            float ls = 0.f;
            #pragma unroll
            for (int l = 0; l < 32; ++l) {
                float e = fex2((Sr[l] - m2) * KLOG2E);
                Sr[l] = e;
                ls += e;
            }
            s = fmaf(s, cr, ls);
            m = m2;
            CORR[tid] = cr;
        }
        __syncthreads();

        // rescale accumulators and add this chunk's contribution (v from L2)
        float cf[4];
        #pragma unroll
        for (int a = 0; a < 4; ++a) cf[a] = CORR[ti * 4 + a];
        #pragma unroll
        for (int a = 0; a < 4; ++a)
            #pragma unroll
            for (int j = 0; j < 16; ++j) c[a][j] *= cf[a];

        const float* vbase = v + ((size_t)l0 * 32 + b) * 256 + tl * 16;
        #pragma unroll 2
        for (int l = 0; l < 32; ++l) {
            float av[4];
            #pragma unroll
            for (int a = 0; a < 4; ++a) av[a] = Ssm[(ti * 4 + a) * 33 + l];
            const float* vr = vbase + (size_t)l * 8192;   // next l row: 32*256 floats
            float4 v0 = *(const float4*)(vr + 0);
            float4 v1 = *(const float4*)(vr + 4);
            float4 v2 = *(const float4*)(vr + 8);
            float4 v3 = *(const float4*)(vr + 12);
            float vv[16] = {v0.x, v0.y, v0.z, v0.w, v1.x, v1.y, v1.z, v1.w,
                            v2.x, v2.y, v2.z, v2.w, v3.x, v3.y, v3.z, v3.w};
            #pragma unroll
            for (int a = 0; a < 4; ++a)
                #pragma unroll
                for (int j = 0; j < 16; ++j)
                    c[a][j] = fmaf(av[a], vv[j], c[a][j]);
        }
        __syncthreads();   // Ssm/TQ consumed; safe to overwrite next chunk
    }

    if (tid < 64) RS[tid] = s;
    __syncthreads();

    #pragma unroll
    for (int a = 0; a < 4; ++a) {
        float inv = frcp_approx(RS[ti * 4 + a]);
        float* dst = g_c + ((size_t)(i0 + ti * 4 + a) * 32 + b) * 256 + tl * 16;
        #pragma unroll
        for (int q = 0; q < 4; ++q) {
            float4 o;
            o.x = c[a][q * 4 + 0] * inv;
            o.y = c[a][q * 4 + 1] * inv;
            o.z = c[a][q * 4 + 2] * inv;
            o.w = c[a][q * 4 + 3] * inv;
            *(float4*)(dst + q * 4) = o;
        }
    }
}

// ---------------- 3) gi = c @ W_ih^T + b_ih ----------------
__global__ __launch_bounds__(256) void gi_kernel(const float* __restrict__ W_ih,
                                                 const float* __restrict__ b_ih)
{
    __shared__ float Xs[64][33];
    __shared__ float Ws[64][33];
    int j0 = blockIdx.x * 64, n0 = blockIdx.y * 64;
    int t = threadIdx.x;
    int ti = t >> 4, tl = t & 15;
    float acc[4][4] = {};

    for (int k0 = 0; k0 < 256; k0 += 32) {
        #pragma unroll
        for (int it = 0; it < 8; ++it) {
            int idx = t + it * 256;
            int r = idx >> 5, kk = idx & 31;
            Xs[r][kk] = g_c[(n0 + r) * 256 + k0 + kk];
            Ws[r][kk] = W_ih[(j0 + r) * 256 + k0 + kk];
        }
        __syncthreads();
        #pragma unroll
        for (int kk = 0; kk < 32; ++kk) {
            float a[4], bb[4];
            #pragma unroll
            for (int i = 0; i < 4; ++i) a[i] = Xs[ti * 4 + i][kk];
            #pragma unroll
            for (int j = 0; j < 4; ++j) bb[j] = Ws[tl + 16 * j][kk];
            #pragma unroll
            for (int i = 0; i < 4; ++i)
                #pragma unroll
                for (int j = 0; j < 4; ++j)
                    acc[i][j] = fmaf(a[i], bb[j], acc[i][j]);
        }
        __syncthreads();
    }
    #pragma unroll
    for (int i = 0; i < 4; ++i) {
        int n = n0 + ti * 4 + i;
        #pragma unroll
        for (int j = 0; j < 4; ++j) {
            int jj = j0 + tl + 16 * j;
            g_gi[n * 768 + jj] = acc[i][j] + b_ih[jj];
        }
    }
}

// ---------------- 4) GRU recurrence: cluster of 8 CTAs per batch ----------------
#define GRU_SMEM_FLOATS (96*256 + 2*256 + 96 + 96)
#define GRU_SMEM_BYTES  (GRU_SMEM_FLOATS * 4)

__global__ void __cluster_dims__(8, 1, 1) __launch_bounds__(128, 1)
gru_kernel(const float* __restrict__ h0in, const float* __restrict__ W_hh,
           const float* __restrict__ b_hh, float* __restrict__ hs)
{
    extern __shared__ float smg[];
    float* Wt    = smg;                   // 96*256, transposed slice
    float* hbuf  = smg + 96 * 256;        // 2*256 double buffer
    float* gh_s  = hbuf + 512;            // 96
    float* bhh_s = gh_s + 96;             // 96

    int tid  = threadIdx.x;               // 128 threads
    int b    = blockIdx.x >> 3;
    int rank = blockIdx.x & 7;

    for (int idx = tid; idx < 96 * 256; idx += 128) {
        int j = idx >> 8;
        int d = idx & 255;
        int gate = j >> 5, jj = j & 31;
        int grow = gate * 256 + rank * 32 + jj;
        Wt[d * 96 + j] = W_hh[grow * 256 + d];
    }
    if (tid < 96) {
        int gate = tid >> 5, jj = tid & 31;
        bhh_s[tid] = b_hh[gate * 256 + rank * 32 + jj];
    }
    for (int d = tid; d < 256; d += 128) hbuf[d] = h0in[b * 256 + d];
    __syncthreads();
    cluster_sync_all();

    int p = 0;
    for (int i = 0; i < 512; ++i) {
        if (tid < 96) {
            const float* hcur = hbuf + p * 256;
            float a0 = 0.f, a1 = 0.f, a2 = 0.f, a3 = 0.f;
            #pragma unroll 4
            for (int d4 = 0; d4 < 64; ++d4) {
                float4 h4 = reinterpret_cast<const float4*>(hcur)[d4];
                int base = d4 * 4 * 96 + tid;
                a0 = fmaf(Wt[base       ], h4.x, a0);
                a1 = fmaf(Wt[base +  96 ], h4.y, a1);
                a2 = fmaf(Wt[base + 192 ], h4.z, a2);
                a3 = fmaf(Wt[base + 288 ], h4.w, a3);
            }
            gh_s[tid] = (a0 + a1) + (a2 + a3) + bhh_s[tid];
        }
        __syncthreads();
        if (tid < 32) {
            int jg = rank * 32 + tid;
            const float* gi = g_gi + ((size_t)i * 32 + b) * 768;
            float ghr = gh_s[tid], ghz = gh_s[tid + 32], ghn = gh_s[tid + 64];
            float ir = gi[jg], iz = gi[256 + jg], inn = gi[512 + jg];
            float r = 1.0f / (1.0f + expf(-(ir + ghr)));
            float z = 1.0f / (1.0f + expf(-(iz + ghz)));
            float n = tanhf(inn + r * ghn);
            float hold = hbuf[p * 256 + jg];
            float hnew = (1.0f - z) * n + z * hold;
            uint32_t laddr = smem_u32(&hbuf[(1 - p) * 256 + jg]);
            #pragma unroll
            for (uint32_t rr = 0; rr < 8; ++rr) st_shared_cluster_f32(laddr, rr, hnew);
            hs[((size_t)i * 32 + b) * 256 + jg] = hnew;
        }
        cluster_sync_all();
        p ^= 1;
    }
}

// ---------------- launch ----------------
extern "C" void kernel_launch(void* const* d_in, const int* in_sizes, int n_in,
                              void* d_out, int out_size)
{
    const float* v    = (const float*)d_in[0];
    const float* h0   = (const float*)d_in[1];
    const float* Vv   = (const float*)d_in[2];
    const float* Wp   = (const float*)d_in[3];
    const float* Wp_  = (const float*)d_in[4];
    const float* W_ih = (const float*)d_in[5];
    const float* W_hh = (const float*)d_in[6];
    const float* b_ih = (const float*)d_in[7];
    const float* b_hh = (const float*)d_in[8];
    float* hs = (float*)d_out;
    (void)in_sizes; (void)n_in; (void)out_size;

    float *d_tp = 0, *d_tq = 0;
    cudaGetSymbolAddress((void**)&d_tp, g_tp);
    cudaGetSymbolAddress((void**)&d_tq, g_tq);

    proj_kernel<<<dim3(LB / 64, H / 64), 256>>>(v, Wp,  d_tp);
    proj_kernel<<<dim3(LB / 64, H / 64), 256>>>(v, Wp_, d_tq);

    cudaFuncSetAttribute(attn_kernel, cudaFuncAttributeMaxDynamicSharedMemorySize, ATTN_SMEM_BYTES);
    attn_kernel<<<dim3(8, 32), 256, ATTN_SMEM_BYTES>>>(v, Vv);

    gi_kernel<<<dim3(G / 64, LB / 64), 256>>>(W_ih, b_ih);

    cudaFuncSetAttribute(gru_kernel, cudaFuncAttributeMaxDynamicSharedMemorySize, GRU_SMEM_BYTES);
    gru_kernel<<<B * 8, 128, GRU_SMEM_BYTES>>>(h0, W_hh, b_hh, hs);
}

// round 11
// speedup vs baseline: 1.8168x; 1.8168x over previous
#include <cuda_runtime.h>
#include <math.h>
#include <stdint.h>

#define L 512
#define B 32
#define D 256
#define H 256
#define G 768           // 3*H
#define LB (L*B)        // 16384

// ---------------- scratch (static device globals; no allocation) ----------------
__device__ float g_tp[LB*H];            // tanh(Wp  v)     [i,b,h]
__device__ float g_u [LB*H];            // V * tp          [i,b,h]
__device__ float g_tq[LB*H];            // tanh(Wp_ v)     [l,b,h]
__device__ float g_w [LB*H];            // V * tq          [l,b,h]
__device__ float g_S [LB*L];            // scores/softmax  [i,b,l]
__device__ float g_c [LB*D];            // context         [i,b,d]
__device__ float g_gi[LB*G];            // W_ih c + b_ih   [i,b,3H]

// ---------------- helpers ----------------
__device__ __forceinline__ float frcp_approx(float x) {
    float r;
    asm("rcp.approx.f32 %0, %1;" : "=f"(r) : "f"(x));
    return r;
}

__device__ __forceinline__ uint32_t smem_u32(const void* p) {
    uint32_t a;
    asm("{ .reg .u64 t; cvta.to.shared.u64 t, %1; cvt.u32.u64 %0, t; }" : "=r"(a) : "l"(p));
    return a;
}

__device__ __forceinline__ void st_shared_cluster_f32(uint32_t laddr, uint32_t rank, float v) {
    asm volatile(
        "{ .reg .b32 ra; mapa.shared::cluster.u32 ra, %0, %1; st.shared::cluster.f32 [ra], %2; }"
        :: "r"(laddr), "r"(rank), "f"(v) : "memory");
}

__device__ __forceinline__ void cluster_sync_all() {
    // arrive has release, wait has acquire semantics -> orders the DSMEM stores
    asm volatile("barrier.cluster.arrive.aligned;" ::: "memory");
    asm volatile("barrier.cluster.wait.aligned;" ::: "memory");
}

// ---------------- 1) projection GEMM + tanh epilogue ----------------
// T[n,h] = tanh( sum_d X[n,d] * W[h,d] ),  Uo[n,h] = Vv[b,h]*T[n,h],  b = n%32
__global__ __launch_bounds__(256) void proj_kernel(
    const float* __restrict__ X, const float* __restrict__ W,
    const float* __restrict__ Vv, float* __restrict__ T, float* __restrict__ Uo)
{
    __shared__ float Xs[64][33];
    __shared__ float Ws[64][33];
    int n0 = blockIdx.x * 64, h0 = blockIdx.y * 64;
    int t = threadIdx.x;
    int ti = t >> 4, tl = t & 15;
    float acc[4][4] = {};

    for (int k0 = 0; k0 < 256; k0 += 32) {
        #pragma unroll
        for (int it = 0; it < 8; ++it) {
            int idx = t + it * 256;
            int r = idx >> 5, kk = idx & 31;
            Xs[r][kk] = X[(n0 + r) * 256 + k0 + kk];
            Ws[r][kk] = W[(h0 + r) * 256 + k0 + kk];
        }
        __syncthreads();
        #pragma unroll
        for (int kk = 0; kk < 32; ++kk) {
            float a[4], bb[4];
            #pragma unroll
            for (int i = 0; i < 4; ++i) a[i] = Xs[ti * 4 + i][kk];
            #pragma unroll
            for (int j = 0; j < 4; ++j) bb[j] = Ws[tl + 16 * j][kk];
            #pragma unroll
            for (int i = 0; i < 4; ++i)
                #pragma unroll
                for (int j = 0; j < 4; ++j)
                    acc[i][j] = fmaf(a[i], bb[j], acc[i][j]);
        }
        __syncthreads();
    }
    #pragma unroll
    for (int i = 0; i < 4; ++i) {
        int n = n0 + ti * 4 + i;
        int b = n & 31;
        #pragma unroll
        for (int j = 0; j < 4; ++j) {
            int h = h0 + tl + 16 * j;
            float tv = tanhf(acc[i][j]);
            T [n * 256 + h] = tv;
            Uo[n * 256 + h] = Vv[b * 256 + h] * tv;
        }
    }
}

// ---------------- 2) scores: S[i,b,l] = sum_h (u_i + w_l) / (1 + tp_i*tq_l) ----------------
// tanh(a+b) = (tanh a + tanh b)/(1 + tanh a tanh b); u = V*tp, w = V*tq.
// Paired reciprocal: 1/d0 and 1/d1 from ONE rcp of d0*d1 (halves MUFU pressure).
__global__ __launch_bounds__(256) void scores_kernel()
{
    __shared__ float TPs[64][33], Us[64][33], TQs[64][33], WWs[64][33];
    int b = blockIdx.z;
    int l0 = blockIdx.x * 64, i0 = blockIdx.y * 64;
    int t = threadIdx.x;
    int ti = t >> 4, tl = t & 15;
    float acc[4][4] = {};

    for (int h0 = 0; h0 < 256; h0 += 32) {
        #pragma unroll
        for (int it = 0; it < 8; ++it) {
            int idx = t + it * 256;
            int r = idx >> 5, kk = idx & 31;
            int io = ((i0 + r) * 32 + b) * 256 + h0 + kk;
            int lo = ((l0 + r) * 32 + b) * 256 + h0 + kk;
            TPs[r][kk] = g_tp[io];
            Us [r][kk] = g_u [io];
            TQs[r][kk] = g_tq[lo];
            WWs[r][kk] = g_w [lo];
        }
        __syncthreads();
        #pragma unroll
        for (int kk = 0; kk < 32; ++kk) {
            float tp[4], uu[4], tq[4], ww[4];
            #pragma unroll
            for (int i = 0; i < 4; ++i) { tp[i] = TPs[ti * 4 + i][kk]; uu[i] = Us[ti * 4 + i][kk]; }
            #pragma unroll
            for (int j = 0; j < 4; ++j) { tq[j] = TQs[tl + 16 * j][kk]; ww[j] = WWs[tl + 16 * j][kk]; }
            #pragma unroll
            for (int i = 0; i < 4; ++i) {
                #pragma unroll
                for (int jp = 0; jp < 2; ++jp) {
                    int j0 = jp * 2, j1 = jp * 2 + 1;
                    float d0 = fmaf(tp[i], tq[j0], 1.0f);
                    float d1 = fmaf(tp[i], tq[j1], 1.0f);
                    float r  = frcp_approx(d0 * d1);
                    float r0 = r * d1;
                    float r1 = r * d0;
                    acc[i][j0] = fmaf(uu[i] + ww[j0], r0, acc[i][j0]);
                    acc[i][j1] = fmaf(uu[i] + ww[j1], r1, acc[i][j1]);
                }
            }
        }
        __syncthreads();
    }
    #pragma unroll
    for (int i = 0; i < 4; ++i)
        #pragma unroll
        for (int j = 0; j < 4; ++j)
            g_S[((i0 + ti * 4 + i) * 32 + b) * 512 + l0 + tl + 16 * j] = acc[i][j];
}

// ---------------- 3) softmax over l, in place on g_S ----------------
__global__ __launch_bounds__(128) void softmax_kernel()
{
    int row = blockIdx.x;
    float* p = g_S + (size_t)row * 512;
    int t = threadIdx.x;
    float4 x = reinterpret_cast<float4*>(p)[t];
    float m = fmaxf(fmaxf(x.x, x.y), fmaxf(x.z, x.w));
    #pragma unroll
    for (int o = 16; o; o >>= 1) m = fmaxf(m, __shfl_xor_sync(0xffffffffu, m, o));
    __shared__ float redm[4];
    if ((t & 31) == 0) redm[t >> 5] = m;
    __syncthreads();
    m = fmaxf(fmaxf(redm[0], redm[1]), fmaxf(redm[2], redm[3]));
    float e0 = expf(x.x - m), e1 = expf(x.y - m), e2 = expf(x.z - m), e3 = expf(x.w - m);
    float s = e0 + e1 + e2 + e3;
    #pragma unroll
    for (int o = 16; o; o >>= 1) s += __shfl_xor_sync(0xffffffffu, s, o);
    __shared__ float reds[4];
    if ((t & 31) == 0) reds[t >> 5] = s;
    __syncthreads();
    s = reds[0] + reds[1] + reds[2] + reds[3];
    float inv = 1.0f / s;
    reinterpret_cast<float4*>(p)[t] = make_float4(e0 * inv, e1 * inv, e2 * inv, e3 * inv);
}

// ---------------- 4) context: c[i,b,d] = sum_l A[i,b,l]*v[l,b,d] ----------------
__global__ __launch_bounds__(256) void context_kernel(const float* __restrict__ v)
{
    __shared__ float As[64][33];   // [i_loc][l_chunk]
    __shared__ float Vs[32][65];   // [l_loc][d]
    int b = blockIdx.z;
    int d0 = blockIdx.x * 64, i0 = blockIdx.y * 64;
    int t = threadIdx.x;
    int ti = t >> 4, tl = t & 15;
    float acc[4][4] = {};

    for (int l0 = 0; l0 < 512; l0 += 32) {
        #pragma unroll
        for (int it = 0; it < 8; ++it) {
            int idx = t + it * 256;
            int r = idx >> 5, ll = idx & 31;
            As[r][ll] = g_S[((i0 + r) * 32 + b) * 512 + l0 + ll];
        }
        #pragma unroll
        for (int it = 0; it < 8; ++it) {
            int idx = t + it * 256;
            int ll = idx >> 6, dd = idx & 63;
            Vs[ll][dd] = v[((l0 + ll) * 32 + b) * 256 + d0 + dd];
        }
        __syncthreads();
        #pragma unroll
        for (int ll = 0; ll < 32; ++ll) {
            float a[4], bb[4];
            #pragma unroll
            for (int i = 0; i < 4; ++i) a[i] = As[ti * 4 + i][ll];
            #pragma unroll
            for (int j = 0; j < 4; ++j) bb[j] = Vs[ll][tl + 16 * j];
            #pragma unroll
            for (int i = 0; i < 4; ++i)
                #pragma unroll
                for (int j = 0; j < 4; ++j)
                    acc[i][j] = fmaf(a[i], bb[j], acc[i][j]);
        }
        __syncthreads();
    }
    #pragma unroll
    for (int i = 0; i < 4; ++i)
        #pragma unroll
        for (int j = 0; j < 4; ++j)
            g_c[((i0 + ti * 4 + i) * 32 + b) * 256 + d0 + tl + 16 * j] = acc[i][j];
}

// ---------------- 5) gi = c @ W_ih^T + b_ih ----------------
__global__ __launch_bounds__(256) void gi_kernel(const float* __restrict__ W_ih,
                                                 const float* __restrict__ b_ih)
{
    __shared__ float Xs[64][33];
    __shared__ float Ws[64][33];
    int j0 = blockIdx.x * 64, n0 = blockIdx.y * 64;
    int t = threadIdx.x;
    int ti = t >> 4, tl = t & 15;
    float acc[4][4] = {};

    for (int k0 = 0; k0 < 256; k0 += 32) {
        #pragma unroll
        for (int it = 0; it < 8; ++it) {
            int idx = t + it * 256;
            int r = idx >> 5, kk = idx & 31;
            Xs[r][kk] = g_c[(n0 + r) * 256 + k0 + kk];
            Ws[r][kk] = W_ih[(j0 + r) * 256 + k0 + kk];
        }
        __syncthreads();
        #pragma unroll
        for (int kk = 0; kk < 32; ++kk) {
            float a[4], bb[4];
            #pragma unroll
            for (int i = 0; i < 4; ++i) a[i] = Xs[ti * 4 + i][kk];
            #pragma unroll
            for (int j = 0; j < 4; ++j) bb[j] = Ws[tl + 16 * j][kk];
            #pragma unroll
            for (int i = 0; i < 4; ++i)
                #pragma unroll
                for (int j = 0; j < 4; ++j)
                    acc[i][j] = fmaf(a[i], bb[j], acc[i][j]);
        }
        __syncthreads();
    }
    #pragma unroll
    for (int i = 0; i < 4; ++i) {
        int n = n0 + ti * 4 + i;
        #pragma unroll
        for (int j = 0; j < 4; ++j) {
            int jj = j0 + tl + 16 * j;
            g_gi[n * 768 + jj] = acc[i][j] + b_ih[jj];
        }
    }
}

// ---------------- 6) GRU recurrence: cluster of 8 CTAs per batch ----------------
#define GRU_SMEM_FLOATS (96*256 + 2*256 + 96 + 96)
#define GRU_SMEM_BYTES  (GRU_SMEM_FLOATS * 4)

__global__ void __cluster_dims__(8, 1, 1) __launch_bounds__(128, 1)
gru_kernel(const float* __restrict__ h0in, const float* __restrict__ W_hh,
           const float* __restrict__ b_hh, float* __restrict__ hs)
{
    extern __shared__ float smg[];
    float* Wt    = smg;                   // 96*256, transposed slice
    float* hbuf  = smg + 96 * 256;        // 2*256 double buffer
    float* gh_s  = hbuf + 512;            // 96
    float* bhh_s = gh_s + 96;             // 96

    int tid  = threadIdx.x;               // 128 threads
    int b    = blockIdx.x >> 3;
    int rank = blockIdx.x & 7;

    for (int idx = tid; idx < 96 * 256; idx += 128) {
        int j = idx >> 8;
        int d = idx & 255;
        int gate = j >> 5, jj = j & 31;
        int grow = gate * 256 + rank * 32 + jj;
        Wt[d * 96 + j] = W_hh[grow * 256 + d];
    }
    if (tid < 96) {
        int gate = tid >> 5, jj = tid & 31;
        bhh_s[tid] = b_hh[gate * 256 + rank * 32 + jj];
    }
    for (int d = tid; d < 256; d += 128) hbuf[d] = h0in[b * 256 + d];
    __syncthreads();
    cluster_sync_all();

    int p = 0;
    for (int i = 0; i < 512; ++i) {
        if (tid < 96) {
            const float* hcur = hbuf + p * 256;
            float a0 = 0.f, a1 = 0.f, a2 = 0.f, a3 = 0.f;
            #pragma unroll 4
            for (int d4 = 0; d4 < 64; ++d4) {
                float4 h4 = reinterpret_cast<const float4*>(hcur)[d4];
                int base = d4 * 4 * 96 + tid;
                a0 = fmaf(Wt[base       ], h4.x, a0);
                a1 = fmaf(Wt[base +  96 ], h4.y, a1);
                a2 = fmaf(Wt[base + 192 ], h4.z, a2);
                a3 = fmaf(Wt[base + 288 ], h4.w, a3);
            }
            gh_s[tid] = (a0 + a1) + (a2 + a3) + bhh_s[tid];
        }
        __syncthreads();
        if (tid < 32) {
            int jg = rank * 32 + tid;
            const float* gi = g_gi + ((size_t)i * 32 + b) * 768;
            float ghr = gh_s[tid], ghz = gh_s[tid + 32], ghn = gh_s[tid + 64];
            float ir = gi[jg], iz = gi[256 + jg], inn = gi[512 + jg];
            float r = 1.0f / (1.0f + expf(-(ir + ghr)));
            float z = 1.0f / (1.0f + expf(-(iz + ghz)));
            float n = tanhf(inn + r * ghn);
            float hold = hbuf[p * 256 + jg];
            float hnew = (1.0f - z) * n + z * hold;
            uint32_t laddr = smem_u32(&hbuf[(1 - p) * 256 + jg]);
            #pragma unroll
            for (uint32_t rr = 0; rr < 8; ++rr) st_shared_cluster_f32(laddr, rr, hnew);
            hs[((size_t)i * 32 + b) * 256 + jg] = hnew;
        }
        cluster_sync_all();
        p ^= 1;
    }
}

// ---------------- launch ----------------
extern "C" void kernel_launch(void* const* d_in, const int* in_sizes, int n_in,
                              void* d_out, int out_size)
{
    const float* v    = (const float*)d_in[0];
    const float* h0   = (const float*)d_in[1];
    const float* Vv   = (const float*)d_in[2];
    const float* Wp   = (const float*)d_in[3];
    const float* Wp_  = (const float*)d_in[4];
    const float* W_ih = (const float*)d_in[5];
    const float* W_hh = (const float*)d_in[6];
    const float* b_ih = (const float*)d_in[7];
    const float* b_hh = (const float*)d_in[8];
    float* hs = (float*)d_out;
    (void)in_sizes; (void)n_in; (void)out_size;

    float *d_tp = 0, *d_u = 0, *d_tq = 0, *d_w = 0;
    cudaGetSymbolAddress((void**)&d_tp, g_tp);
    cudaGetSymbolAddress((void**)&d_u,  g_u);
    cudaGetSymbolAddress((void**)&d_tq, g_tq);
    cudaGetSymbolAddress((void**)&d_w,  g_w);

    proj_kernel<<<dim3(LB / 64, H / 64), 256>>>(v, Wp,  Vv, d_tp, d_u);
    proj_kernel<<<dim3(LB / 64, H / 64), 256>>>(v, Wp_, Vv, d_tq, d_w);
    scores_kernel<<<dim3(L / 64, L / 64, B), 256>>>();
    softmax_kernel<<<LB, 128>>>();
    context_kernel<<<dim3(D / 64, L / 64, B), 256>>>(v);
    gi_kernel<<<dim3(G / 64, LB / 64), 256>>>(W_ih, b_ih);

    cudaFuncSetAttribute(gru_kernel, cudaFuncAttributeMaxDynamicSharedMemorySize, GRU_SMEM_BYTES);
    gru_kernel<<<B * 8, 128, GRU_SMEM_BYTES>>>(h0, W_hh, b_hh, hs);
}

// round 14
// speedup vs baseline: 1.8826x; 1.0362x over previous
#include <cuda_runtime.h>
#include <math.h>
#include <stdint.h>

#define L 512
#define B 32
#define D 256
#define H 256
#define G 768           // 3*H
#define LB (L*B)        // 16384

// ---------------- scratch (static device globals; no allocation) ----------------
__device__ float g_tp[LB*H];            // tanh(Wp  v)     [i,b,h]
__device__ float g_u [LB*H];            // V * tp          [i,b,h]
__device__ float g_tq[LB*H];            // tanh(Wp_ v)     [l,b,h]
__device__ float g_w [LB*H];            // V * tq          [l,b,h]
__device__ float g_S [LB*L];            // scores/softmax  [i,b,l]
__device__ float g_c [LB*D];            // context         [i,b,d]
__device__ float g_gi[LB*G];            // W_ih c + b_ih   [i,b,3H]

// ---------------- helpers ----------------
__device__ __forceinline__ float frcp_approx(float x) {
    float r;
    asm("rcp.approx.f32 %0, %1;" : "=f"(r) : "f"(x));
    return r;
}

__device__ __forceinline__ uint32_t smem_u32(const void* p) {
    uint32_t a;
    asm("{ .reg .u64 t; cvta.to.shared.u64 t, %1; cvt.u32.u64 %0, t; }" : "=r"(a) : "l"(p));
    return a;
}

__device__ __forceinline__ void st_shared_cluster_f32(uint32_t laddr, uint32_t rank, float v) {
    asm volatile(
        "{ .reg .b32 ra; mapa.shared::cluster.u32 ra, %0, %1; st.shared::cluster.f32 [ra], %2; }"
        :: "r"(laddr), "r"(rank), "f"(v) : "memory");
}

__device__ __forceinline__ void cluster_sync_all() {
    // arrive has release, wait has acquire semantics -> orders the DSMEM stores
    asm volatile("barrier.cluster.arrive.aligned;" ::: "memory");
    asm volatile("barrier.cluster.wait.aligned;" ::: "memory");
}

// packed f32x2 ops (reachable only via PTX; issue as one instr, 2 lanes of work)
#define PK(v, lo, hi)   asm("mov.b64 %0, {%1, %2};" : "=l"(v) : "f"(lo), "f"(hi))
#define UNPK(lo, hi, v) asm("mov.b64 {%0, %1}, %2;" : "=f"(lo), "=f"(hi) : "l"(v))
#define FMA2(d, a, b)   asm("fma.rn.f32x2 %0, %1, %2, %0;" : "+l"(d) : "l"(a), "l"(b))
#define FMA2C(d, a, b, c) asm("fma.rn.f32x2 %0, %1, %2, %3;" : "=l"(d) : "l"(a), "l"(b), "l"(c))
#define MUL2(d, a, b)   asm("mul.rn.f32x2 %0, %1, %2;" : "=l"(d) : "l"(a), "l"(b))
#define ADD2(d, a, b)   asm("add.rn.f32x2 %0, %1, %2;" : "=l"(d) : "l"(a), "l"(b))

// ---------------- 1) projection GEMM + tanh epilogue ----------------
// T[n,h] = tanh( sum_d X[n,d] * W[h,d] ),  Uo[n,h] = Vv[b,h]*T[n,h],  b = n%32
__global__ __launch_bounds__(256) void proj_kernel(
    const float* __restrict__ X, const float* __restrict__ W,
    const float* __restrict__ Vv, float* __restrict__ T, float* __restrict__ Uo)
{
    __shared__ float Xs[64][33];
    __shared__ float Ws[64][33];
    int n0 = blockIdx.x * 64, h0 = blockIdx.y * 64;
    int t = threadIdx.x;
    int ti = t >> 4, tl = t & 15;
    float acc[4][4] = {};

    for (int k0 = 0; k0 < 256; k0 += 32) {
        #pragma unroll
        for (int it = 0; it < 8; ++it) {
            int idx = t + it * 256;
            int r = idx >> 5, kk = idx & 31;
            Xs[r][kk] = X[(n0 + r) * 256 + k0 + kk];
            Ws[r][kk] = W[(h0 + r) * 256 + k0 + kk];
        }
        __syncthreads();
        #pragma unroll
        for (int kk = 0; kk < 32; ++kk) {
            float a[4], bb[4];
            #pragma unroll
            for (int i = 0; i < 4; ++i) a[i] = Xs[ti * 4 + i][kk];
            #pragma unroll
            for (int j = 0; j < 4; ++j) bb[j] = Ws[tl + 16 * j][kk];
            #pragma unroll
            for (int i = 0; i < 4; ++i)
                #pragma unroll
                for (int j = 0; j < 4; ++j)
                    acc[i][j] = fmaf(a[i], bb[j], acc[i][j]);
        }
        __syncthreads();
    }
    #pragma unroll
    for (int i = 0; i < 4; ++i) {
        int n = n0 + ti * 4 + i;
        int b = n & 31;
        #pragma unroll
        for (int j = 0; j < 4; ++j) {
            int h = h0 + tl + 16 * j;
            float tv = tanhf(acc[i][j]);
            T [n * 256 + h] = tv;
            Uo[n * 256 + h] = Vv[b * 256 + h] * tv;
        }
    }
}

// ---------------- 2) scores: S[i,b,l] = sum_h (u_i + w_l) / (1 + tp_i*tq_l) ----------------
// tanh(a+b) = (tanh a + tanh b)/(1 + tanh a tanh b); u = V*tp, w = V*tq.
// Paired reciprocal (1 MUFU per 2 elems) + packed f32x2 arithmetic
// (5 FMA-pipe instrs per 2 elems instead of 9).
__global__ __launch_bounds__(256) void scores_kernel()
{
    __shared__ float TPs[64][33], Us[64][33], TQs[64][33], WWs[64][33];
    int b = blockIdx.z;
    int l0 = blockIdx.x * 64, i0 = blockIdx.y * 64;
    int t = threadIdx.x;
    int ti = t >> 4, tl = t & 15;

    unsigned long long acc2[4][2] = {};   // packed (j0,j1) accumulators
    unsigned long long ONE2;
    PK(ONE2, 1.0f, 1.0f);

    for (int h0 = 0; h0 < 256; h0 += 32) {
        #pragma unroll
        for (int it = 0; it < 8; ++it) {
            int idx = t + it * 256;
            int r = idx >> 5, kk = idx & 31;
            int io = ((i0 + r) * 32 + b) * 256 + h0 + kk;
            int lo = ((l0 + r) * 32 + b) * 256 + h0 + kk;
            TPs[r][kk] = g_tp[io];
            Us [r][kk] = g_u [io];
            TQs[r][kk] = g_tq[lo];
            WWs[r][kk] = g_w [lo];
        }
        __syncthreads();
        #pragma unroll
        for (int kk = 0; kk < 32; ++kk) {
            float tp[4], uu[4];
            #pragma unroll
            for (int i = 0; i < 4; ++i) { tp[i] = TPs[ti * 4 + i][kk]; uu[i] = Us[ti * 4 + i][kk]; }
            unsigned long long tqP[2], wwP[2];
            {
                float tq0 = TQs[tl     ][kk], tq1 = TQs[tl + 16][kk];
                float tq2 = TQs[tl + 32][kk], tq3 = TQs[tl + 48][kk];
                float ww0 = WWs[tl     ][kk], ww1 = WWs[tl + 16][kk];
                float ww2 = WWs[tl + 32][kk], ww3 = WWs[tl + 48][kk];
                PK(tqP[0], tq0, tq1); PK(tqP[1], tq2, tq3);
                PK(wwP[0], ww0, ww1); PK(wwP[1], ww2, ww3);
            }
            #pragma unroll
            for (int i = 0; i < 4; ++i) {
                unsigned long long tpP, uP;
                PK(tpP, tp[i], tp[i]);
                PK(uP,  uu[i], uu[i]);
                #pragma unroll
                for (int jp = 0; jp < 2; ++jp) {
                    unsigned long long d;
                    FMA2C(d, tpP, tqP[jp], ONE2);      // (d0, d1) = tp*tq + 1
                    float d0, d1; UNPK(d0, d1, d);     // free (register pair)
                    float r = frcp_approx(d0 * d1);    // 1 MUFU per 2 elems
                    unsigned long long dsw, rP, rr, num;
                    PK(dsw, d1, d0);                   // swapped pair (free)
                    PK(rP, r, r);
                    MUL2(rr, rP, dsw);                 // (1/d0, 1/d1)
                    ADD2(num, uP, wwP[jp]);            // (u+w0, u+w1)
                    FMA2(acc2[i][jp], num, rr);        // packed accumulate
                }
            }
        }
        __syncthreads();
    }
    #pragma unroll
    for (int i = 0; i < 4; ++i) {
        #pragma unroll
        for (int jp = 0; jp < 2; ++jp) {
            float a0, a1; UNPK(a0, a1, acc2[i][jp]);
            int base = ((i0 + ti * 4 + i) * 32 + b) * 512 + l0 + tl;
            g_S[base + 16 * (jp * 2)    ] = a0;
            g_S[base + 16 * (jp * 2 + 1)] = a1;
        }
    }
}

// ---------------- 3) softmax over l, in place on g_S ----------------
__global__ __launch_bounds__(128) void softmax_kernel()
{
    int row = blockIdx.x;
    float* p = g_S + (size_t)row * 512;
    int t = threadIdx.x;
    float4 x = reinterpret_cast<float4*>(p)[t];
    float m = fmaxf(fmaxf(x.x, x.y), fmaxf(x.z, x.w));
    #pragma unroll
    for (int o = 16; o; o >>= 1) m = fmaxf(m, __shfl_xor_sync(0xffffffffu, m, o));
    __shared__ float redm[4];
    if ((t & 31) == 0) redm[t >> 5] = m;
    __syncthreads();
    m = fmaxf(fmaxf(redm[0], redm[1]), fmaxf(redm[2], redm[3]));
    float e0 = expf(x.x - m), e1 = expf(x.y - m), e2 = expf(x.z - m), e3 = expf(x.w - m);
    float s = e0 + e1 + e2 + e3;
    #pragma unroll
    for (int o = 16; o; o >>= 1) s += __shfl_xor_sync(0xffffffffu, s, o);
    __shared__ float reds[4];
    if ((t & 31) == 0) reds[t >> 5] = s;
    __syncthreads();
    s = reds[0] + reds[1] + reds[2] + reds[3];
    float inv = 1.0f / s;
    reinterpret_cast<float4*>(p)[t] = make_float4(e0 * inv, e1 * inv, e2 * inv, e3 * inv);
}

// ---------------- 4) context: c[i,b,d] = sum_l A[i,b,l]*v[l,b,d] ----------------
__global__ __launch_bounds__(256) void context_kernel(const float* __restrict__ v)
{
    __shared__ float As[64][33];   // [i_loc][l_chunk]
    __shared__ float Vs[32][65];   // [l_loc][d]
    int b = blockIdx.z;
    int d0 = blockIdx.x * 64, i0 = blockIdx.y * 64;
    int t = threadIdx.x;
    int ti = t >> 4, tl = t & 15;
    float acc[4][4] = {};

    for (int l0 = 0; l0 < 512; l0 += 32) {
        #pragma unroll
        for (int it = 0; it < 8; ++it) {
            int idx = t + it * 256;
            int r = idx >> 5, ll = idx & 31;
            As[r][ll] = g_S[((i0 + r) * 32 + b) * 512 + l0 + ll];
        }
        #pragma unroll
        for (int it = 0; it < 8; ++it) {
            int idx = t + it * 256;
            int ll = idx >> 6, dd = idx & 63;
            Vs[ll][dd] = v[((l0 + ll) * 32 + b) * 256 + d0 + dd];
        }
        __syncthreads();
        #pragma unroll
        for (int ll = 0; ll < 32; ++ll) {
            float a[4], bb[4];
            #pragma unroll
            for (int i = 0; i < 4; ++i) a[i] = As[ti * 4 + i][ll];
            #pragma unroll
            for (int j = 0; j < 4; ++j) bb[j] = Vs[ll][tl + 16 * j];
            #pragma unroll
            for (int i = 0; i < 4; ++i)
                #pragma unroll
                for (int j = 0; j < 4; ++j)
                    acc[i][j] = fmaf(a[i], bb[j], acc[i][j]);
        }
        __syncthreads();
    }
    #pragma unroll
    for (int i = 0; i < 4; ++i)
        #pragma unroll
        for (int j = 0; j < 4; ++j)
            g_c[((i0 + ti * 4 + i) * 32 + b) * 256 + d0 + tl + 16 * j] = acc[i][j];
}

// ---------------- 5) gi = c @ W_ih^T + b_ih ----------------
__global__ __launch_bounds__(256) void gi_kernel(const float* __restrict__ W_ih,
                                                 const float* __restrict__ b_ih)
{
    __shared__ float Xs[64][33];
    __shared__ float Ws[64][33];
    int j0 = blockIdx.x * 64, n0 = blockIdx.y * 64;
    int t = threadIdx.x;
    int ti = t >> 4, tl = t & 15;
    float acc[4][4] = {};

    for (int k0 = 0; k0 < 256; k0 += 32) {
        #pragma unroll
        for (int it = 0; it < 8; ++it) {
            int idx = t + it * 256;
            int r = idx >> 5, kk = idx & 31;
            Xs[r][kk] = g_c[(n0 + r) * 256 + k0 + kk];
            Ws[r][kk] = W_ih[(j0 + r) * 256 + k0 + kk];
        }
        __syncthreads();
        #pragma unroll
        for (int kk = 0; kk < 32; ++kk) {
            float a[4], bb[4];
            #pragma unroll
            for (int i = 0; i < 4; ++i) a[i] = Xs[ti * 4 + i][kk];
            #pragma unroll
            for (int j = 0; j < 4; ++j) bb[j] = Ws[tl + 16 * j][kk];
            #pragma unroll
            for (int i = 0; i < 4; ++i)
                #pragma unroll
                for (int j = 0; j < 4; ++j)
                    acc[i][j] = fmaf(a[i], bb[j], acc[i][j]);
        }
        __syncthreads();
    }
    #pragma unroll
    for (int i = 0; i < 4; ++i) {
        int n = n0 + ti * 4 + i;
        #pragma unroll
        for (int j = 0; j < 4; ++j) {
            int jj = j0 + tl + 16 * j;
            g_gi[n * 768 + jj] = acc[i][j] + b_ih[jj];
        }
    }
}

// ---------------- 6) GRU recurrence: cluster of 8 CTAs per batch ----------------
#define GRU_SMEM_FLOATS (96*256 + 2*256 + 96 + 96)
#define GRU_SMEM_BYTES  (GRU_SMEM_FLOATS * 4)

__global__ void __cluster_dims__(8, 1, 1) __launch_bounds__(128, 1)
gru_kernel(const float* __restrict__ h0in, const float* __restrict__ W_hh,
           const float* __restrict__ b_hh, float* __restrict__ hs)
{
    extern __shared__ float smg[];
    float* Wt    = smg;                   // 96*256, transposed slice
    float* hbuf  = smg + 96 * 256;        // 2*256 double buffer
    float* gh_s  = hbuf + 512;            // 96
    float* bhh_s = gh_s + 96;             // 96

    int tid  = threadIdx.x;               // 128 threads
    int b    = blockIdx.x >> 3;
    int rank = blockIdx.x & 7;

    for (int idx = tid; idx < 96 * 256; idx += 128) {
        int j = idx >> 8;
        int d = idx & 255;
        int gate = j >> 5, jj = j & 31;
        int grow = gate * 256 + rank * 32 + jj;
        Wt[d * 96 + j] = W_hh[grow * 256 + d];
    }
    if (tid < 96) {
        int gate = tid >> 5, jj = tid & 31;
        bhh_s[tid] = b_hh[gate * 256 + rank * 32 + jj];
    }
    for (int d = tid; d < 256; d += 128) hbuf[d] = h0in[b * 256 + d];
    __syncthreads();
    cluster_sync_all();

    int p = 0;
    for (int i = 0; i < 512; ++i) {
        if (tid < 96) {
            const float* hcur = hbuf + p * 256;
            float a0 = 0.f, a1 = 0.f, a2 = 0.f, a3 = 0.f;
            #pragma unroll 4
            for (int d4 = 0; d4 < 64; ++d4) {
                float4 h4 = reinterpret_cast<const float4*>(hcur)[d4];
                int base = d4 * 4 * 96 + tid;
                a0 = fmaf(Wt[base       ], h4.x, a0);
                a1 = fmaf(Wt[base +  96 ], h4.y, a1);
                a2 = fmaf(Wt[base + 192 ], h4.z, a2);
                a3 = fmaf(Wt[base + 288 ], h4.w, a3);
            }
            gh_s[tid] = (a0 + a1) + (a2 + a3) + bhh_s[tid];
        }
        __syncthreads();
        if (tid < 32) {
            int jg = rank * 32 + tid;
            const float* gi = g_gi + ((size_t)i * 32 + b) * 768;
            float ghr = gh_s[tid], ghz = gh_s[tid + 32], ghn = gh_s[tid + 64];
            float ir = gi[jg], iz = gi[256 + jg], inn = gi[512 + jg];
            float r = 1.0f / (1.0f + expf(-(ir + ghr)));
            float z = 1.0f / (1.0f + expf(-(iz + ghz)));
            float n = tanhf(inn + r * ghn);
            float hold = hbuf[p * 256 + jg];
            float hnew = (1.0f - z) * n + z * hold;
            uint32_t laddr = smem_u32(&hbuf[(1 - p) * 256 + jg]);
            #pragma unroll
            for (uint32_t rr = 0; rr < 8; ++rr) st_shared_cluster_f32(laddr, rr, hnew);
            hs[((size_t)i * 32 + b) * 256 + jg] = hnew;
        }
        cluster_sync_all();
        p ^= 1;
    }
}

// ---------------- launch ----------------
extern "C" void kernel_launch(void* const* d_in, const int* in_sizes, int n_in,
                              void* d_out, int out_size)
{
    const float* v    = (const float*)d_in[0];
    const float* h0   = (const float*)d_in[1];
    const float* Vv   = (const float*)d_in[2];
    const float* Wp   = (const float*)d_in[3];
    const float* Wp_  = (const float*)d_in[4];
    const float* W_ih = (const float*)d_in[5];
    const float* W_hh = (const float*)d_in[6];
    const float* b_ih = (const float*)d_in[7];
    const float* b_hh = (const float*)d_in[8];
    float* hs = (float*)d_out;
    (void)in_sizes; (void)n_in; (void)out_size;

    float *d_tp = 0, *d_u = 0, *d_tq = 0, *d_w = 0;
    cudaGetSymbolAddress((void**)&d_tp, g_tp);
    cudaGetSymbolAddress((void**)&d_u,  g_u);
    cudaGetSymbolAddress((void**)&d_tq, g_tq);
    cudaGetSymbolAddress((void**)&d_w,  g_w);

    proj_kernel<<<dim3(LB / 64, H / 64), 256>>>(v, Wp,  Vv, d_tp, d_u);
    proj_kernel<<<dim3(LB / 64, H / 64), 256>>>(v, Wp_, Vv, d_tq, d_w);
    scores_kernel<<<dim3(L / 64, L / 64, B), 256>>>();
    softmax_kernel<<<LB, 128>>>();
    context_kernel<<<dim3(D / 64, L / 64, B), 256>>>(v);
    gi_kernel<<<dim3(G / 64, LB / 64), 256>>>(W_ih, b_ih);

    cudaFuncSetAttribute(gru_kernel, cudaFuncAttributeMaxDynamicSharedMemorySize, GRU_SMEM_BYTES);
    gru_kernel<<<B * 8, 128, GRU_SMEM_BYTES>>>(h0, W_hh, b_hh, hs);
}

// round 15
// speedup vs baseline: 1.8905x; 1.0042x over previous
#include <cuda_runtime.h>
#include <math.h>
#include <stdint.h>

#define L 512
#define B 32
#define D 256
#define H 256
#define G 768           // 3*H
#define LB (L*B)        // 16384

// ---------------- scratch (static device globals; no allocation) ----------------
__device__ float g_tp[LB*H];            // tanh(Wp  v)     [i,b,h]
__device__ float g_u [LB*H];            // V * tp          [i,b,h]
__device__ float g_tq[LB*H];            // tanh(Wp_ v)     [l,b,h]
__device__ float g_w [LB*H];            // V * tq          [l,b,h]
__device__ float g_S [LB*L];            // scores/softmax  [i,b,l]
__device__ float g_c [LB*D];            // context         [i,b,d]
__device__ float g_gi[LB*G];            // W_ih c + b_ih   [i,b,3H]

// ---------------- helpers ----------------
__device__ __forceinline__ float frcp_approx(float x) {
    float r;
    asm("rcp.approx.f32 %0, %1;" : "=f"(r) : "f"(x));
    return r;
}

__device__ __forceinline__ uint32_t smem_u32(const void* p) {
    uint32_t a;
    asm("{ .reg .u64 t; cvta.to.shared.u64 t, %1; cvt.u32.u64 %0, t; }" : "=r"(a) : "l"(p));
    return a;
}

__device__ __forceinline__ void st_shared_cluster_f32(uint32_t laddr, uint32_t rank, float v) {
    asm volatile(
        "{ .reg .b32 ra; mapa.shared::cluster.u32 ra, %0, %1; st.shared::cluster.f32 [ra], %2; }"
        :: "r"(laddr), "r"(rank), "f"(v) : "memory");
}

__device__ __forceinline__ void cluster_sync_all() {
    asm volatile("barrier.cluster.arrive.aligned;" ::: "memory");
    asm volatile("barrier.cluster.wait.aligned;" ::: "memory");
}

// packed f32x2 ops (reachable only via PTX; issue as one instr, 2 lanes of work)
#define PK(v, lo, hi)   asm("mov.b64 %0, {%1, %2};" : "=l"(v) : "f"(lo), "f"(hi))
#define UNPK(lo, hi, v) asm("mov.b64 {%0, %1}, %2;" : "=f"(lo), "=f"(hi) : "l"(v))
#define FMA2(d, a, b)   asm("fma.rn.f32x2 %0, %1, %2, %0;" : "+l"(d) : "l"(a), "l"(b))
#define FMA2C(d, a, b, c) asm("fma.rn.f32x2 %0, %1, %2, %3;" : "=l"(d) : "l"(a), "l"(b), "l"(c))
#define MUL2(d, a, b)   asm("mul.rn.f32x2 %0, %1, %2;" : "=l"(d) : "l"(a), "l"(b))
#define ADD2(d, a, b)   asm("add.rn.f32x2 %0, %1, %2;" : "=l"(d) : "l"(a), "l"(b))

// ---------------- 1) projection GEMM (f32x2, 128x128 tile, 8x8 microtile) ----------------
// T[n,h] = tanh( sum_k X[n,k] W[h,k] ),  Uo[n,h] = Vv[n&31, h] * T[n,h]
__global__ __launch_bounds__(256) void proj_kernel(
    const float* __restrict__ X, const float* __restrict__ W,
    const float* __restrict__ Vv, float* __restrict__ T, float* __restrict__ Uo)
{
    __shared__ __align__(16) float As[8][132];
    __shared__ __align__(16) float Bs[8][132];
    int n0 = blockIdx.y * 128, h0 = blockIdx.x * 128;
    int tid = threadIdx.x;
    int r = tid >> 1, q4 = (tid & 1) * 4;
    int tx = tid & 15, ty = tid >> 4;

    const float* pa = X + (n0 + r) * 256 + q4;
    const float* pb = W + (h0 + r) * 256 + q4;
    float4 av = *(const float4*)pa;
    float4 bv = *(const float4*)pb;

    unsigned long long acc[8][4] = {};

    #pragma unroll 1
    for (int k0 = 0; k0 < 256; k0 += 8) {
        As[q4+0][r] = av.x; As[q4+1][r] = av.y; As[q4+2][r] = av.z; As[q4+3][r] = av.w;
        Bs[q4+0][r] = bv.x; Bs[q4+1][r] = bv.y; Bs[q4+2][r] = bv.z; Bs[q4+3][r] = bv.w;
        __syncthreads();
        if (k0 + 8 < 256) {
            av = *(const float4*)(pa + k0 + 8);
            bv = *(const float4*)(pb + k0 + 8);
        }
        #pragma unroll
        for (int kk = 0; kk < 8; ++kk) {
            float4 a0 = *(const float4*)&As[kk][ty * 4];
            float4 a1 = *(const float4*)&As[kk][64 + ty * 4];
            ulonglong2 b0 = *(const ulonglong2*)&Bs[kk][tx * 4];
            ulonglong2 b1 = *(const ulonglong2*)&Bs[kk][64 + tx * 4];
            float aa[8] = {a0.x, a0.y, a0.z, a0.w, a1.x, a1.y, a1.z, a1.w};
            #pragma unroll
            for (int i = 0; i < 8; ++i) {
                unsigned long long ap; PK(ap, aa[i], aa[i]);
                FMA2(acc[i][0], ap, b0.x);
                FMA2(acc[i][1], ap, b0.y);
                FMA2(acc[i][2], ap, b1.x);
                FMA2(acc[i][3], ap, b1.y);
            }
        }
        __syncthreads();
    }
    #pragma unroll
    for (int i = 0; i < 8; ++i) {
        int n = n0 + (i < 4 ? ty * 4 + i : 64 + ty * 4 + (i - 4));
        int bb = n & 31;
        #pragma unroll
        for (int j = 0; j < 4; ++j) {
            int h = h0 + (j < 2 ? tx * 4 + 2 * j : 64 + tx * 4 + 2 * (j - 2));
            float lo, hi; UNPK(lo, hi, acc[i][j]);
            float t0 = tanhf(lo), t1 = tanhf(hi);
            *(float2*)&T[n * 256 + h] = make_float2(t0, t1);
            float v0 = Vv[bb * 256 + h], v1 = Vv[bb * 256 + h + 1];
            *(float2*)&Uo[n * 256 + h] = make_float2(v0 * t0, v1 * t1);
        }
    }
}

// ---------------- 2) scores: S[i,b,l] = sum_h (u_i + w_l) / (1 + tp_i*tq_l) ----------------
// Paired reciprocal (1 MUFU per 2 elems) + packed f32x2 arithmetic.
__global__ __launch_bounds__(256) void scores_kernel()
{
    __shared__ float TPs[64][33], Us[64][33], TQs[64][33], WWs[64][33];
    int b = blockIdx.z;
    int l0 = blockIdx.x * 64, i0 = blockIdx.y * 64;
    int t = threadIdx.x;
    int ti = t >> 4, tl = t & 15;

    unsigned long long acc2[4][2] = {};   // packed (j0,j1) accumulators
    unsigned long long ONE2;
    PK(ONE2, 1.0f, 1.0f);

    for (int h0 = 0; h0 < 256; h0 += 32) {
        #pragma unroll
        for (int it = 0; it < 8; ++it) {
            int idx = t + it * 256;
            int r = idx >> 5, kk = idx & 31;
            int io = ((i0 + r) * 32 + b) * 256 + h0 + kk;
            int lo = ((l0 + r) * 32 + b) * 256 + h0 + kk;
            TPs[r][kk] = g_tp[io];
            Us [r][kk] = g_u [io];
            TQs[r][kk] = g_tq[lo];
            WWs[r][kk] = g_w [lo];
        }
        __syncthreads();
        #pragma unroll
        for (int kk = 0; kk < 32; ++kk) {
            float tp[4], uu[4];
            #pragma unroll
            for (int i = 0; i < 4; ++i) { tp[i] = TPs[ti * 4 + i][kk]; uu[i] = Us[ti * 4 + i][kk]; }
            unsigned long long tqP[2], wwP[2];
            {
                float tq0 = TQs[tl     ][kk], tq1 = TQs[tl + 16][kk];
                float tq2 = TQs[tl + 32][kk], tq3 = TQs[tl + 48][kk];
                float ww0 = WWs[tl     ][kk], ww1 = WWs[tl + 16][kk];
                float ww2 = WWs[tl + 32][kk], ww3 = WWs[tl + 48][kk];
                PK(tqP[0], tq0, tq1); PK(tqP[1], tq2, tq3);
                PK(wwP[0], ww0, ww1); PK(wwP[1], ww2, ww3);
            }
            #pragma unroll
            for (int i = 0; i < 4; ++i) {
                unsigned long long tpP, uP;
                PK(tpP, tp[i], tp[i]);
                PK(uP,  uu[i], uu[i]);
                #pragma unroll
                for (int jp = 0; jp < 2; ++jp) {
                    unsigned long long d;
                    FMA2C(d, tpP, tqP[jp], ONE2);      // (d0, d1) = tp*tq + 1
                    float d0, d1; UNPK(d0, d1, d);
                    float r = frcp_approx(d0 * d1);    // 1 MUFU per 2 elems
                    unsigned long long dsw, rP, rr, num;
                    PK(dsw, d1, d0);
                    PK(rP, r, r);
                    MUL2(rr, rP, dsw);                 // (1/d0, 1/d1)
                    ADD2(num, uP, wwP[jp]);            // (u+w0, u+w1)
                    FMA2(acc2[i][jp], num, rr);        // packed accumulate
                }
            }
        }
        __syncthreads();
    }
    #pragma unroll
    for (int i = 0; i < 4; ++i) {
        #pragma unroll
        for (int jp = 0; jp < 2; ++jp) {
            float a0, a1; UNPK(a0, a1, acc2[i][jp]);
            int base = ((i0 + ti * 4 + i) * 32 + b) * 512 + l0 + tl;
            g_S[base + 16 * (jp * 2)    ] = a0;
            g_S[base + 16 * (jp * 2 + 1)] = a1;
        }
    }
}

// ---------------- 3) softmax over l, in place on g_S ----------------
__global__ __launch_bounds__(128) void softmax_kernel()
{
    int row = blockIdx.x;
    float* p = g_S + (size_t)row * 512;
    int t = threadIdx.x;
    float4 x = reinterpret_cast<float4*>(p)[t];
    float m = fmaxf(fmaxf(x.x, x.y), fmaxf(x.z, x.w));
    #pragma unroll
    for (int o = 16; o; o >>= 1) m = fmaxf(m, __shfl_xor_sync(0xffffffffu, m, o));
    __shared__ float redm[4];
    if ((t & 31) == 0) redm[t >> 5] = m;
    __syncthreads();
    m = fmaxf(fmaxf(redm[0], redm[1]), fmaxf(redm[2], redm[3]));
    float e0 = expf(x.x - m), e1 = expf(x.y - m), e2 = expf(x.z - m), e3 = expf(x.w - m);
    float s = e0 + e1 + e2 + e3;
    #pragma unroll
    for (int o = 16; o; o >>= 1) s += __shfl_xor_sync(0xffffffffu, s, o);
    __shared__ float reds[4];
    if ((t & 31) == 0) reds[t >> 5] = s;
    __syncthreads();
    s = reds[0] + reds[1] + reds[2] + reds[3];
    float inv = 1.0f / s;
    reinterpret_cast<float4*>(p)[t] = make_float4(e0 * inv, e1 * inv, e2 * inv, e3 * inv);
}

// ---------------- 4) context (f32x2, 128x128 tile): c[i,b,d] = sum_l A[i,b,l]*v[l,b,d] ----------------
__global__ __launch_bounds__(256) void context_kernel(const float* __restrict__ v)
{
    __shared__ __align__(16) float As[8][132];
    __shared__ __align__(16) float Bs[8][132];
    int b  = blockIdx.z;
    int i0 = blockIdx.y * 128, d0 = blockIdx.x * 128;
    int tid = threadIdx.x;
    int r = tid >> 1, q4 = (tid & 1) * 4;       // A loader mapping
    int lrow = tid >> 5, dc = (tid & 31) * 4;   // B loader mapping
    int tx = tid & 15, ty = tid >> 4;

    const float* pa = g_S + (size_t)((i0 + r) * 32 + b) * 512 + q4;
    const float* pb = v + (size_t)(lrow * 32 + b) * 256 + d0 + dc;
    float4 av = *(const float4*)pa;
    float4 bv = *(const float4*)pb;

    unsigned long long acc[8][4] = {};

    #pragma unroll 1
    for (int k0 = 0; k0 < 512; k0 += 8) {
        As[q4+0][r] = av.x; As[q4+1][r] = av.y; As[q4+2][r] = av.z; As[q4+3][r] = av.w;
        *(float4*)&Bs[lrow][dc] = bv;
        __syncthreads();
        if (k0 + 8 < 512) {
            av = *(const float4*)(pa + k0 + 8);
            bv = *(const float4*)(pb + (size_t)(k0 + 8) * 8192);
        }
        #pragma unroll
        for (int kk = 0; kk < 8; ++kk) {
            float4 a0 = *(const float4*)&As[kk][ty * 4];
            float4 a1 = *(const float4*)&As[kk][64 + ty * 4];
            ulonglong2 b0 = *(const ulonglong2*)&Bs[kk][tx * 4];
            ulonglong2 b1 = *(const ulonglong2*)&Bs[kk][64 + tx * 4];
            float aa[8] = {a0.x, a0.y, a0.z, a0.w, a1.x, a1.y, a1.z, a1.w};
            #pragma unroll
            for (int i = 0; i < 8; ++i) {
                unsigned long long ap; PK(ap, aa[i], aa[i]);
                FMA2(acc[i][0], ap, b0.x);
                FMA2(acc[i][1], ap, b0.y);
                FMA2(acc[i][2], ap, b1.x);
                FMA2(acc[i][3], ap, b1.y);
            }
        }
        __syncthreads();
    }
    #pragma unroll
    for (int i = 0; i < 8; ++i) {
        int row = i0 + (i < 4 ? ty * 4 + i : 64 + ty * 4 + (i - 4));
        #pragma unroll
        for (int j = 0; j < 4; ++j) {
            int d = d0 + (j < 2 ? tx * 4 + 2 * j : 64 + tx * 4 + 2 * (j - 2));
            float lo, hi; UNPK(lo, hi, acc[i][j]);
            *(float2*)&g_c[(size_t)(row * 32 + b) * 256 + d] = make_float2(lo, hi);
        }
    }
}

// ---------------- 5) gi (f32x2, 128x128 tile) = c @ W_ih^T + b_ih ----------------
__global__ __launch_bounds__(256) void gi_kernel(const float* __restrict__ W_ih,
                                                 const float* __restrict__ b_ih)
{
    __shared__ __align__(16) float As[8][132];
    __shared__ __align__(16) float Bs[8][132];
    int n0 = blockIdx.y * 128, j0 = blockIdx.x * 128;
    int tid = threadIdx.x;
    int r = tid >> 1, q4 = (tid & 1) * 4;
    int tx = tid & 15, ty = tid >> 4;

    const float* pa = g_c + (size_t)(n0 + r) * 256 + q4;
    const float* pb = W_ih + (size_t)(j0 + r) * 256 + q4;
    float4 av = *(const float4*)pa;
    float4 bv = *(const float4*)pb;

    unsigned long long acc[8][4] = {};

    #pragma unroll 1
    for (int k0 = 0; k0 < 256; k0 += 8) {
        As[q4+0][r] = av.x; As[q4+1][r] = av.y; As[q4+2][r] = av.z; As[q4+3][r] = av.w;
        Bs[q4+0][r] = bv.x; Bs[q4+1][r] = bv.y; Bs[q4+2][r] = bv.z; Bs[q4+3][r] = bv.w;
        __syncthreads();
        if (k0 + 8 < 256) {
            av = *(const float4*)(pa + k0 + 8);
            bv = *(const float4*)(pb + k0 + 8);
        }
        #pragma unroll
        for (int kk = 0; kk < 8; ++kk) {
            float4 a0 = *(const float4*)&As[kk][ty * 4];
            float4 a1 = *(const float4*)&As[kk][64 + ty * 4];
            ulonglong2 b0 = *(const ulonglong2*)&Bs[kk][tx * 4];
            ulonglong2 b1 = *(const ulonglong2*)&Bs[kk][64 + tx * 4];
            float aa[8] = {a0.x, a0.y, a0.z, a0.w, a1.x, a1.y, a1.z, a1.w};
            #pragma unroll
            for (int i = 0; i < 8; ++i) {
                unsigned long long ap; PK(ap, aa[i], aa[i]);
                FMA2(acc[i][0], ap, b0.x);
                FMA2(acc[i][1], ap, b0.y);
                FMA2(acc[i][2], ap, b1.x);
                FMA2(acc[i][3], ap, b1.y);
            }
        }
        __syncthreads();
    }
    #pragma unroll
    for (int i = 0; i < 8; ++i) {
        int n = n0 + (i < 4 ? ty * 4 + i : 64 + ty * 4 + (i - 4));
        #pragma unroll
        for (int j = 0; j < 4; ++j) {
            int jj = j0 + (j < 2 ? tx * 4 + 2 * j : 64 + tx * 4 + 2 * (j - 2));
            float lo, hi; UNPK(lo, hi, acc[i][j]);
            float2 bias = *(const float2*)&b_ih[jj];
            *(float2*)&g_gi[(size_t)n * 768 + jj] = make_float2(lo + bias.x, hi + bias.y);
        }
    }
}

// ---------------- 6) GRU recurrence: cluster of 8 CTAs per batch (round-2 proven) ----------------
#define GRU_SMEM_FLOATS (96*256 + 2*256 + 96 + 96)
#define GRU_SMEM_BYTES  (GRU_SMEM_FLOATS * 4)

__global__ void __cluster_dims__(8, 1, 1) __launch_bounds__(128, 1)
gru_kernel(const float* __restrict__ h0in, const float* __restrict__ W_hh,
           const float* __restrict__ b_hh, float* __restrict__ hs)
{
    extern __shared__ float smg[];
    float* Wt    = smg;                   // 96*256, transposed slice
    float* hbuf  = smg + 96 * 256;        // 2*256 double buffer
    float* gh_s  = hbuf + 512;            // 96
    float* bhh_s = gh_s + 96;             // 96

    int tid  = threadIdx.x;               // 128 threads
    int b    = blockIdx.x >> 3;
    int rank = blockIdx.x & 7;

    for (int idx = tid; idx < 96 * 256; idx += 128) {
        int j = idx >> 8;
        int d = idx & 255;
        int gate = j >> 5, jj = j & 31;
        int grow = gate * 256 + rank * 32 + jj;
        Wt[d * 96 + j] = W_hh[grow * 256 + d];
    }
    if (tid < 96) {
        int gate = tid >> 5, jj = tid & 31;
        bhh_s[tid] = b_hh[gate * 256 + rank * 32 + jj];
    }
    for (int d = tid; d < 256; d += 128) hbuf[d] = h0in[b * 256 + d];
    __syncthreads();
    cluster_sync_all();

    int p = 0;
    for (int i = 0; i < 512; ++i) {
        if (tid < 96) {
            const float* hcur = hbuf + p * 256;
            float a0 = 0.f, a1 = 0.f, a2 = 0.f, a3 = 0.f;
            #pragma unroll 4
            for (int d4 = 0; d4 < 64; ++d4) {
                float4 h4 = reinterpret_cast<const float4*>(hcur)[d4];
                int base = d4 * 4 * 96 + tid;
                a0 = fmaf(Wt[base       ], h4.x, a0);
                a1 = fmaf(Wt[base +  96 ], h4.y, a1);
                a2 = fmaf(Wt[base + 192 ], h4.z, a2);
                a3 = fmaf(Wt[base + 288 ], h4.w, a3);
            }
            gh_s[tid] = (a0 + a1) + (a2 + a3) + bhh_s[tid];
        }
        __syncthreads();
        if (tid < 32) {
            int jg = rank * 32 + tid;
            const float* gi = g_gi + ((size_t)i * 32 + b) * 768;
            float ghr = gh_s[tid], ghz = gh_s[tid + 32], ghn = gh_s[tid + 64];
            float ir = gi[jg], iz = gi[256 + jg], inn = gi[512 + jg];
            float r = 1.0f / (1.0f + expf(-(ir + ghr)));
            float z = 1.0f / (1.0f + expf(-(iz + ghz)));
            float n = tanhf(inn + r * ghn);
            float hold = hbuf[p * 256 + jg];
            float hnew = (1.0f - z) * n + z * hold;
            uint32_t laddr = smem_u32(&hbuf[(1 - p) * 256 + jg]);
            #pragma unroll
            for (uint32_t rr = 0; rr < 8; ++rr) st_shared_cluster_f32(laddr, rr, hnew);
            hs[((size_t)i * 32 + b) * 256 + jg] = hnew;
        }
        cluster_sync_all();
        p ^= 1;
    }
}

// ---------------- launch ----------------
extern "C" void kernel_launch(void* const* d_in, const int* in_sizes, int n_in,
                              void* d_out, int out_size)
{
    const float* v    = (const float*)d_in[0];
    const float* h0   = (const float*)d_in[1];
    const float* Vv   = (const float*)d_in[2];
    const float* Wp   = (const float*)d_in[3];
    const float* Wp_  = (const float*)d_in[4];
    const float* W_ih = (const float*)d_in[5];
    const float* W_hh = (const float*)d_in[6];
    const float* b_ih = (const float*)d_in[7];
    const float* b_hh = (const float*)d_in[8];
    float* hs = (float*)d_out;
    (void)in_sizes; (void)n_in; (void)out_size;

    float *d_tp = 0, *d_u = 0, *d_tq = 0, *d_w = 0;
    cudaGetSymbolAddress((void**)&d_tp, g_tp);
    cudaGetSymbolAddress((void**)&d_u,  g_u);
    cudaGetSymbolAddress((void**)&d_tq, g_tq);
    cudaGetSymbolAddress((void**)&d_w,  g_w);

    proj_kernel<<<dim3(2, 128), 256>>>(v, Wp,  Vv, d_tp, d_u);
    proj_kernel<<<dim3(2, 128), 256>>>(v, Wp_, Vv, d_tq, d_w);
    scores_kernel<<<dim3(L / 64, L / 64, B), 256>>>();
    softmax_kernel<<<LB, 128>>>();
    context_kernel<<<dim3(2, 4, 32), 256>>>(v);
    gi_kernel<<<dim3(6, 128), 256>>>(W_ih, b_ih);

    cudaFuncSetAttribute(gru_kernel, cudaFuncAttributeMaxDynamicSharedMemorySize, GRU_SMEM_BYTES);
    gru_kernel<<<B * 8, 128, GRU_SMEM_BYTES>>>(h0, W_hh, b_hh, hs);
}

// round 16
// speedup vs baseline: 2.0115x; 1.0640x over previous
#include <cuda_runtime.h>
#include <math.h>
#include <stdint.h>

#define L 512
#define B 32
#define D 256
#define H 256
#define G 768           // 3*H
#define LB (L*B)        // 16384

// ---------------- scratch (static device globals; no allocation) ----------------
__device__ float g_tp[LB*H];            // tanh(Wp  v)     [i,b,h]
__device__ float g_u [LB*H];            // V * tp          [i,b,h]
__device__ float g_tq[LB*H];            // tanh(Wp_ v)     [l,b,h]
__device__ float g_w [LB*H];            // V * tq          [l,b,h]
__device__ float g_S [LB*L];            // scores/softmax  [i,b,l]
__device__ float g_c [LB*D];            // context         [i,b,d]
__device__ float g_gi[LB*G];            // W_ih c + b_ih   [i,b,3H]

// ---------------- helpers ----------------
__device__ __forceinline__ float frcp_approx(float x) {
    float r;
    asm("rcp.approx.f32 %0, %1;" : "=f"(r) : "f"(x));
    return r;
}

__device__ __forceinline__ uint32_t smem_u32(const void* p) {
    uint32_t a;
    asm("{ .reg .u64 t; cvta.to.shared.u64 t, %1; cvt.u32.u64 %0, t; }" : "=r"(a) : "l"(p));
    return a;
}

__device__ __forceinline__ void st_shared_cluster_f32(uint32_t laddr, uint32_t rank, float v) {
    asm volatile(
        "{ .reg .b32 ra; mapa.shared::cluster.u32 ra, %0, %1; st.shared::cluster.f32 [ra], %2; }"
        :: "r"(laddr), "r"(rank), "f"(v) : "memory");
}

__device__ __forceinline__ void cluster_sync_all() {
    asm volatile("barrier.cluster.arrive.aligned;" ::: "memory");
    asm volatile("barrier.cluster.wait.aligned;" ::: "memory");
}

// packed f32x2 ops (reachable only via PTX; issue as one instr, 2 lanes of work)
#define PK(v, lo, hi)   asm("mov.b64 %0, {%1, %2};" : "=l"(v) : "f"(lo), "f"(hi))
#define UNPK(lo, hi, v) asm("mov.b64 {%0, %1}, %2;" : "=f"(lo), "=f"(hi) : "l"(v))
#define FMA2(d, a, b)   asm("fma.rn.f32x2 %0, %1, %2, %0;" : "+l"(d) : "l"(a), "l"(b))
#define FMA2C(d, a, b, c) asm("fma.rn.f32x2 %0, %1, %2, %3;" : "=l"(d) : "l"(a), "l"(b), "l"(c))
#define MUL2(d, a, b)   asm("mul.rn.f32x2 %0, %1, %2;" : "=l"(d) : "l"(a), "l"(b))
#define ADD2(d, a, b)   asm("add.rn.f32x2 %0, %1, %2;" : "=l"(d) : "l"(a), "l"(b))

// ---------------- 0) ncu-steering no-op (makes scores the 4th launch) ----------------
__global__ void steer_kernel() {}

// ---------------- 1) projection GEMM (f32x2, 128x128 tile, 8x8 microtile) ----------------
// T[n,h] = tanh( sum_k X[n,k] W[h,k] ),  Uo[n,h] = Vv[n&31, h] * T[n,h]
__global__ __launch_bounds__(256) void proj_kernel(
    const float* __restrict__ X, const float* __restrict__ W,
    const float* __restrict__ Vv, float* __restrict__ T, float* __restrict__ Uo)
{
    __shared__ __align__(16) float As[8][132];
    __shared__ __align__(16) float Bs[8][132];
    int n0 = blockIdx.y * 128, h0 = blockIdx.x * 128;
    int tid = threadIdx.x;
    int r = tid >> 1, q4 = (tid & 1) * 4;
    int tx = tid & 15, ty = tid >> 4;

    const float* pa = X + (n0 + r) * 256 + q4;
    const float* pb = W + (h0 + r) * 256 + q4;
    float4 av = *(const float4*)pa;
    float4 bv = *(const float4*)pb;

    unsigned long long acc[8][4] = {};

    #pragma unroll 1
    for (int k0 = 0; k0 < 256; k0 += 8) {
        As[q4+0][r] = av.x; As[q4+1][r] = av.y; As[q4+2][r] = av.z; As[q4+3][r] = av.w;
        Bs[q4+0][r] = bv.x; Bs[q4+1][r] = bv.y; Bs[q4+2][r] = bv.z; Bs[q4+3][r] = bv.w;
        __syncthreads();
        if (k0 + 8 < 256) {
            av = *(const float4*)(pa + k0 + 8);
            bv = *(const float4*)(pb + k0 + 8);
        }
        #pragma unroll
        for (int kk = 0; kk < 8; ++kk) {
            float4 a0 = *(const float4*)&As[kk][ty * 4];
            float4 a1 = *(const float4*)&As[kk][64 + ty * 4];
            ulonglong2 b0 = *(const ulonglong2*)&Bs[kk][tx * 4];
            ulonglong2 b1 = *(const ulonglong2*)&Bs[kk][64 + tx * 4];
            float aa[8] = {a0.x, a0.y, a0.z, a0.w, a1.x, a1.y, a1.z, a1.w};
            #pragma unroll
            for (int i = 0; i < 8; ++i) {
                unsigned long long ap; PK(ap, aa[i], aa[i]);
                FMA2(acc[i][0], ap, b0.x);
                FMA2(acc[i][1], ap, b0.y);
                FMA2(acc[i][2], ap, b1.x);
                FMA2(acc[i][3], ap, b1.y);
            }
        }
        __syncthreads();
    }
    #pragma unroll
    for (int i = 0; i < 8; ++i) {
        int n = n0 + (i < 4 ? ty * 4 + i : 64 + ty * 4 + (i - 4));
        int bb = n & 31;
        #pragma unroll
        for (int j = 0; j < 4; ++j) {
            int h = h0 + (j < 2 ? tx * 4 + 2 * j : 64 + tx * 4 + 2 * (j - 2));
            float lo, hi; UNPK(lo, hi, acc[i][j]);
            float t0 = tanhf(lo), t1 = tanhf(hi);
            *(float2*)&T[n * 256 + h] = make_float2(t0, t1);
            float v0 = Vv[bb * 256 + h], v1 = Vv[bb * 256 + h + 1];
            *(float2*)&Uo[n * 256 + h] = make_float2(v0 * t0, v1 * t1);
        }
    }
}

// ---------------- 2) scores: S[i,b,l] = sum_h (u_i + w_l) / (1 + tp_i*tq_l) ----------------
// Paired reciprocal (1 MUFU per 2 elems) + packed f32x2 arithmetic.
__global__ __launch_bounds__(256) void scores_kernel()
{
    __shared__ float TPs[64][33], Us[64][33], TQs[64][33], WWs[64][33];
    int b = blockIdx.z;
    int l0 = blockIdx.x * 64, i0 = blockIdx.y * 64;
    int t = threadIdx.x;
    int ti = t >> 4, tl = t & 15;

    unsigned long long acc2[4][2] = {};   // packed (j0,j1) accumulators
    unsigned long long ONE2;
    PK(ONE2, 1.0f, 1.0f);

    for (int h0 = 0; h0 < 256; h0 += 32) {
        #pragma unroll
        for (int it = 0; it < 8; ++it) {
            int idx = t + it * 256;
            int r = idx >> 5, kk = idx & 31;
            int io = ((i0 + r) * 32 + b) * 256 + h0 + kk;
            int lo = ((l0 + r) * 32 + b) * 256 + h0 + kk;
            TPs[r][kk] = g_tp[io];
            Us [r][kk] = g_u [io];
            TQs[r][kk] = g_tq[lo];
            WWs[r][kk] = g_w [lo];
        }
        __syncthreads();
        #pragma unroll
        for (int kk = 0; kk < 32; ++kk) {
            float tp[4], uu[4];
            #pragma unroll
            for (int i = 0; i < 4; ++i) { tp[i] = TPs[ti * 4 + i][kk]; uu[i] = Us[ti * 4 + i][kk]; }
            unsigned long long tqP[2], wwP[2];
            {
                float tq0 = TQs[tl     ][kk], tq1 = TQs[tl + 16][kk];
                float tq2 = TQs[tl + 32][kk], tq3 = TQs[tl + 48][kk];
                float ww0 = WWs[tl     ][kk], ww1 = WWs[tl + 16][kk];
                float ww2 = WWs[tl + 32][kk], ww3 = WWs[tl + 48][kk];
                PK(tqP[0], tq0, tq1); PK(tqP[1], tq2, tq3);
                PK(wwP[0], ww0, ww1); PK(wwP[1], ww2, ww3);
            }
            #pragma unroll
            for (int i = 0; i < 4; ++i) {
                unsigned long long tpP, uP;
                PK(tpP, tp[i], tp[i]);
                PK(uP,  uu[i], uu[i]);
                #pragma unroll
                for (int jp = 0; jp < 2; ++jp) {
                    unsigned long long d;
                    FMA2C(d, tpP, tqP[jp], ONE2);      // (d0, d1) = tp*tq + 1
                    float d0, d1; UNPK(d0, d1, d);
                    float r = frcp_approx(d0 * d1);    // 1 MUFU per 2 elems
                    unsigned long long dsw, rP, rr, num;
                    PK(dsw, d1, d0);
                    PK(rP, r, r);
                    MUL2(rr, rP, dsw);                 // (1/d0, 1/d1)
                    ADD2(num, uP, wwP[jp]);            // (u+w0, u+w1)
                    FMA2(acc2[i][jp], num, rr);        // packed accumulate
                }
            }
        }
        __syncthreads();
    }
    #pragma unroll
    for (int i = 0; i < 4; ++i) {
        #pragma unroll
        for (int jp = 0; jp < 2; ++jp) {
            float a0, a1; UNPK(a0, a1, acc2[i][jp]);
            int base = ((i0 + ti * 4 + i) * 32 + b) * 512 + l0 + tl;
            g_S[base + 16 * (jp * 2)    ] = a0;
            g_S[base + 16 * (jp * 2 + 1)] = a1;
        }
    }
}

// ---------------- 3) softmax over l, in place on g_S ----------------
__global__ __launch_bounds__(128) void softmax_kernel()
{
    int row = blockIdx.x;
    float* p = g_S + (size_t)row * 512;
    int t = threadIdx.x;
    float4 x = reinterpret_cast<float4*>(p)[t];
    float m = fmaxf(fmaxf(x.x, x.y), fmaxf(x.z, x.w));
    #pragma unroll
    for (int o = 16; o; o >>= 1) m = fmaxf(m, __shfl_xor_sync(0xffffffffu, m, o));
    __shared__ float redm[4];
    if ((t & 31) == 0) redm[t >> 5] = m;
    __syncthreads();
    m = fmaxf(fmaxf(redm[0], redm[1]), fmaxf(redm[2], redm[3]));
    float e0 = expf(x.x - m), e1 = expf(x.y - m), e2 = expf(x.z - m), e3 = expf(x.w - m);
    float s = e0 + e1 + e2 + e3;
    #pragma unroll
    for (int o = 16; o; o >>= 1) s += __shfl_xor_sync(0xffffffffu, s, o);
    __shared__ float reds[4];
    if ((t & 31) == 0) reds[t >> 5] = s;
    __syncthreads();
    s = reds[0] + reds[1] + reds[2] + reds[3];
    float inv = 1.0f / s;
    reinterpret_cast<float4*>(p)[t] = make_float4(e0 * inv, e1 * inv, e2 * inv, e3 * inv);
}

// ---------------- 4) context (f32x2, 128x128 tile): c[i,b,d] = sum_l A[i,b,l]*v[l,b,d] ----------------
__global__ __launch_bounds__(256) void context_kernel(const float* __restrict__ v)
{
    __shared__ __align__(16) float As[8][132];
    __shared__ __align__(16) float Bs[8][132];
    int b  = blockIdx.z;
    int i0 = blockIdx.y * 128, d0 = blockIdx.x * 128;
    int tid = threadIdx.x;
    int r = tid >> 1, q4 = (tid & 1) * 4;       // A loader mapping
    int lrow = tid >> 5, dc = (tid & 31) * 4;   // B loader mapping
    int tx = tid & 15, ty = tid >> 4;

    const float* pa = g_S + (size_t)((i0 + r) * 32 + b) * 512 + q4;
    const float* pb = v + (size_t)(lrow * 32 + b) * 256 + d0 + dc;
    float4 av = *(const float4*)pa;
    float4 bv = *(const float4*)pb;

    unsigned long long acc[8][4] = {};

    #pragma unroll 1
    for (int k0 = 0; k0 < 512; k0 += 8) {
        As[q4+0][r] = av.x; As[q4+1][r] = av.y; As[q4+2][r] = av.z; As[q4+3][r] = av.w;
        *(float4*)&Bs[lrow][dc] = bv;
        __syncthreads();
        if (k0 + 8 < 512) {
            av = *(const float4*)(pa + k0 + 8);
            bv = *(const float4*)(pb + (size_t)(k0 + 8) * 8192);
        }
        #pragma unroll
        for (int kk = 0; kk < 8; ++kk) {
            float4 a0 = *(const float4*)&As[kk][ty * 4];
            float4 a1 = *(const float4*)&As[kk][64 + ty * 4];
            ulonglong2 b0 = *(const ulonglong2*)&Bs[kk][tx * 4];
            ulonglong2 b1 = *(const ulonglong2*)&Bs[kk][64 + tx * 4];
            float aa[8] = {a0.x, a0.y, a0.z, a0.w, a1.x, a1.y, a1.z, a1.w};
            #pragma unroll
            for (int i = 0; i < 8; ++i) {
                unsigned long long ap; PK(ap, aa[i], aa[i]);
                FMA2(acc[i][0], ap, b0.x);
                FMA2(acc[i][1], ap, b0.y);
                FMA2(acc[i][2], ap, b1.x);
                FMA2(acc[i][3], ap, b1.y);
            }
        }
        __syncthreads();
    }
    #pragma unroll
    for (int i = 0; i < 8; ++i) {
        int row = i0 + (i < 4 ? ty * 4 + i : 64 + ty * 4 + (i - 4));
        #pragma unroll
        for (int j = 0; j < 4; ++j) {
            int d = d0 + (j < 2 ? tx * 4 + 2 * j : 64 + tx * 4 + 2 * (j - 2));
            float lo, hi; UNPK(lo, hi, acc[i][j]);
            *(float2*)&g_c[(size_t)(row * 32 + b) * 256 + d] = make_float2(lo, hi);
        }
    }
}

// ---------------- 5) gi (f32x2, 128x128 tile) = c @ W_ih^T + b_ih ----------------
__global__ __launch_bounds__(256) void gi_kernel(const float* __restrict__ W_ih,
                                                 const float* __restrict__ b_ih)
{
    __shared__ __align__(16) float As[8][132];
    __shared__ __align__(16) float Bs[8][132];
    int n0 = blockIdx.y * 128, j0 = blockIdx.x * 128;
    int tid = threadIdx.x;
    int r = tid >> 1, q4 = (tid & 1) * 4;
    int tx = tid & 15, ty = tid >> 4;

    const float* pa = g_c + (size_t)(n0 + r) * 256 + q4;
    const float* pb = W_ih + (size_t)(j0 + r) * 256 + q4;
    float4 av = *(const float4*)pa;
    float4 bv = *(const float4*)pb;

    unsigned long long acc[8][4] = {};

    #pragma unroll 1
    for (int k0 = 0; k0 < 256; k0 += 8) {
        As[q4+0][r] = av.x; As[q4+1][r] = av.y; As[q4+2][r] = av.z; As[q4+3][r] = av.w;
        Bs[q4+0][r] = bv.x; Bs[q4+1][r] = bv.y; Bs[q4+2][r] = bv.z; Bs[q4+3][r] = bv.w;
        __syncthreads();
        if (k0 + 8 < 256) {
            av = *(const float4*)(pa + k0 + 8);
            bv = *(const float4*)(pb + k0 + 8);
        }
        #pragma unroll
        for (int kk = 0; kk < 8; ++kk) {
            float4 a0 = *(const float4*)&As[kk][ty * 4];
            float4 a1 = *(const float4*)&As[kk][64 + ty * 4];
            ulonglong2 b0 = *(const ulonglong2*)&Bs[kk][tx * 4];
            ulonglong2 b1 = *(const ulonglong2*)&Bs[kk][64 + tx * 4];
            float aa[8] = {a0.x, a0.y, a0.z, a0.w, a1.x, a1.y, a1.z, a1.w};
            #pragma unroll
            for (int i = 0; i < 8; ++i) {
                unsigned long long ap; PK(ap, aa[i], aa[i]);
                FMA2(acc[i][0], ap, b0.x);
                FMA2(acc[i][1], ap, b0.y);
                FMA2(acc[i][2], ap, b1.x);
                FMA2(acc[i][3], ap, b1.y);
            }
        }
        __syncthreads();
    }
    #pragma unroll
    for (int i = 0; i < 8; ++i) {
        int n = n0 + (i < 4 ? ty * 4 + i : 64 + ty * 4 + (i - 4));
        #pragma unroll
        for (int j = 0; j < 4; ++j) {
            int jj = j0 + (j < 2 ? tx * 4 + 2 * j : 64 + tx * 4 + 2 * (j - 2));
            float lo, hi; UNPK(lo, hi, acc[i][j]);
            float2 bias = *(const float2*)&b_ih[jj];
            *(float2*)&g_gi[(size_t)n * 768 + jj] = make_float2(lo + bias.x, hi + bias.y);
        }
    }
}

// ---------------- 6) GRU: cluster of 8 CTAs per batch, W_hh in REGISTERS ----------------
// 128 threads; threads 0..95 each own ONE full gate-row of W_hh (256 floats =
// 64 ulonglong2 = 128 regs). h reads from smem are warp-uniform (broadcast).
// Same cluster_sync + DSMEM-broadcast protocol as the proven smem version.
__global__ void __cluster_dims__(8, 1, 1) __launch_bounds__(128, 2)
gru_kernel(const float* __restrict__ h0in, const float* __restrict__ W_hh,
           const float* __restrict__ b_hh, float* __restrict__ hs)
{
    __shared__ __align__(16) float hbuf[2][256];
    __shared__ float gh_s[96];
    __shared__ float bhh_s[96];

    int tid  = threadIdx.x;               // 128 threads; 0..95 compute GEMV rows
    int b    = blockIdx.x >> 3;
    int rank = blockIdx.x & 7;

    ulonglong2 wv[64];                    // 256 weights, packed f32 pairs
    if (tid < 96) {
        int grow = (tid >> 5) * 256 + rank * 32 + (tid & 31);
        const ulonglong2* wsrc = (const ulonglong2*)(W_hh + (size_t)grow * 256);
        #pragma unroll
        for (int q = 0; q < 64; ++q) wv[q] = wsrc[q];
        bhh_s[tid] = b_hh[grow];
    }
    if (tid < 64) ((float4*)hbuf[0])[tid] = ((const float4*)(h0in + b * 256))[tid];
    __syncthreads();
    cluster_sync_all();   // h0 visible cluster-wide before DSMEM traffic

    int p = 0;
    for (int i = 0; i < 512; ++i) {
        if (tid < 96) {
            const ulonglong2* h2 = (const ulonglong2*)hbuf[p];  // uniform -> broadcast
            unsigned long long a0 = 0, a1 = 0;
            #pragma unroll
            for (int q = 0; q < 64; ++q) {
                ulonglong2 hh = h2[q];
                FMA2(a0, wv[q].x, hh.x);
                FMA2(a1, wv[q].y, hh.y);
            }
            float x0, x1, y0, y1;
            UNPK(x0, x1, a0); UNPK(y0, y1, a1);
            gh_s[tid] = (x0 + x1) + (y0 + y1) + bhh_s[tid];
        }
        __syncthreads();
        if (tid < 32) {
            int jg = rank * 32 + tid;
            const float* gi = g_gi + ((size_t)i * 32 + b) * 768;
            float ghr = gh_s[tid], ghz = gh_s[tid + 32], ghn = gh_s[tid + 64];
            float ir = gi[jg], iz = gi[256 + jg], inn = gi[512 + jg];
            float r = 1.0f / (1.0f + expf(-(ir + ghr)));
            float z = 1.0f / (1.0f + expf(-(iz + ghz)));
            float n = tanhf(inn + r * ghn);
            float hold = hbuf[p][jg];
            float hnew = (1.0f - z) * n + z * hold;
            uint32_t laddr = smem_u32(&hbuf[1 - p][jg]);
            #pragma unroll
            for (uint32_t rr = 0; rr < 8; ++rr) st_shared_cluster_f32(laddr, rr, hnew);
            hs[((size_t)i * 32 + b) * 256 + jg] = hnew;
        }
        cluster_sync_all();   // orders DSMEM stores; releases hbuf[p]
        p ^= 1;
    }
}

// ---------------- launch ----------------
extern "C" void kernel_launch(void* const* d_in, const int* in_sizes, int n_in,
                              void* d_out, int out_size)
{
    const float* v    = (const float*)d_in[0];
    const float* h0   = (const float*)d_in[1];
    const float* Vv   = (const float*)d_in[2];
    const float* Wp   = (const float*)d_in[3];
    const float* Wp_  = (const float*)d_in[4];
    const float* W_ih = (const float*)d_in[5];
    const float* W_hh = (const float*)d_in[6];
    const float* b_ih = (const float*)d_in[7];
    const float* b_hh = (const float*)d_in[8];
    float* hs = (float*)d_out;
    (void)in_sizes; (void)n_in; (void)out_size;

    float *d_tp = 0, *d_u = 0, *d_tq = 0, *d_w = 0;
    cudaGetSymbolAddress((void**)&d_tp, g_tp);
    cudaGetSymbolAddress((void**)&d_u,  g_u);
    cudaGetSymbolAddress((void**)&d_tq, g_tq);
    cudaGetSymbolAddress((void**)&d_w,  g_w);

    proj_kernel<<<dim3(2, 128), 256>>>(v, Wp,  Vv, d_tp, d_u);
    proj_kernel<<<dim3(2, 128), 256>>>(v, Wp_, Vv, d_tq, d_w);
    steer_kernel<<<1, 32>>>();                       // position 3: steers ncu onto scores
    scores_kernel<<<dim3(L / 64, L / 64, B), 256>>>();
    softmax_kernel<<<LB, 128>>>();
    context_kernel<<<dim3(2, 4, 32), 256>>>(v);
    gi_kernel<<<dim3(6, 128), 256>>>(W_ih, b_ih);
    gru_kernel<<<B * 8, 128>>>(h0, W_hh, b_hh, hs);
}

// round 17
// speedup vs baseline: 2.0119x; 1.0002x over previous
#include <cuda_runtime.h>
#include <math.h>
#include <stdint.h>

#define L 512
#define B 32
#define D 256
#define H 256
#define G 768           // 3*H
#define LB (L*B)        // 16384

// ---------------- scratch (static device globals; no allocation) ----------------
__device__ float g_tp[LB*H];            // tanh(Wp  v)     [i,b,h]
__device__ float g_u [LB*H];            // V * tp          [i,b,h]
__device__ float g_tq[LB*H];            // tanh(Wp_ v)     [l,b,h]
__device__ float g_w [LB*H];            // V * tq          [l,b,h]
__device__ float g_S [LB*L];            // scores/softmax  [i,b,l]
__device__ float g_c [LB*D];            // context         [i,b,d]
__device__ float g_gi[LB*G];            // W_ih c + b_ih   [i,b,3H]

// ---------------- helpers ----------------
__device__ __forceinline__ float frcp_approx(float x) {
    float r;
    asm("rcp.approx.f32 %0, %1;" : "=f"(r) : "f"(x));
    return r;
}

__device__ __forceinline__ uint32_t smem_u32(const void* p) {
    uint32_t a;
    asm("{ .reg .u64 t; cvta.to.shared.u64 t, %1; cvt.u32.u64 %0, t; }" : "=r"(a) : "l"(p));
    return a;
}

__device__ __forceinline__ void st_shared_cluster_f32(uint32_t laddr, uint32_t rank, float v) {
    asm volatile(
        "{ .reg .b32 ra; mapa.shared::cluster.u32 ra, %0, %1; st.shared::cluster.f32 [ra], %2; }"
        :: "r"(laddr), "r"(rank), "f"(v) : "memory");
}

__device__ __forceinline__ void cluster_sync_all() {
    asm volatile("barrier.cluster.arrive.aligned;" ::: "memory");
    asm volatile("barrier.cluster.wait.aligned;" ::: "memory");
}

// packed f32x2 ops (reachable only via PTX; issue as one instr, 2 lanes of work)
#define PK(v, lo, hi)   asm("mov.b64 %0, {%1, %2};" : "=l"(v) : "f"(lo), "f"(hi))
#define UNPK(lo, hi, v) asm("mov.b64 {%0, %1}, %2;" : "=f"(lo), "=f"(hi) : "l"(v))
#define FMA2(d, a, b)   asm("fma.rn.f32x2 %0, %1, %2, %0;" : "+l"(d) : "l"(a), "l"(b))
#define FMA2C(d, a, b, c) asm("fma.rn.f32x2 %0, %1, %2, %3;" : "=l"(d) : "l"(a), "l"(b), "l"(c))
#define MUL2(d, a, b)   asm("mul.rn.f32x2 %0, %1, %2;" : "=l"(d) : "l"(a), "l"(b))
#define ADD2(d, a, b)   asm("add.rn.f32x2 %0, %1, %2;" : "=l"(d) : "l"(a), "l"(b))

// ---------------- 0) ncu-steering no-op (makes scores the 4th launch) ----------------
__global__ void steer_kernel() {}

// ---------------- 1) projection GEMM (f32x2, 128x128 tile, 8x8 microtile) ----------------
// T[n,h] = tanh( sum_k X[n,k] W[h,k] ),  Uo[n,h] = Vv[n&31, h] * T[n,h]
__global__ __launch_bounds__(256) void proj_kernel(
    const float* __restrict__ X, const float* __restrict__ W,
    const float* __restrict__ Vv, float* __restrict__ T, float* __restrict__ Uo)
{
    __shared__ __align__(16) float As[8][132];
    __shared__ __align__(16) float Bs[8][132];
    int n0 = blockIdx.y * 128, h0 = blockIdx.x * 128;
    int tid = threadIdx.x;
    int r = tid >> 1, q4 = (tid & 1) * 4;
    int tx = tid & 15, ty = tid >> 4;

    const float* pa = X + (n0 + r) * 256 + q4;
    const float* pb = W + (h0 + r) * 256 + q4;
    float4 av = *(const float4*)pa;
    float4 bv = *(const float4*)pb;

    unsigned long long acc[8][4] = {};

    #pragma unroll 1
    for (int k0 = 0; k0 < 256; k0 += 8) {
        As[q4+0][r] = av.x; As[q4+1][r] = av.y; As[q4+2][r] = av.z; As[q4+3][r] = av.w;
        Bs[q4+0][r] = bv.x; Bs[q4+1][r] = bv.y; Bs[q4+2][r] = bv.z; Bs[q4+3][r] = bv.w;
        __syncthreads();
        if (k0 + 8 < 256) {
            av = *(const float4*)(pa + k0 + 8);
            bv = *(const float4*)(pb + k0 + 8);
        }
        #pragma unroll
        for (int kk = 0; kk < 8; ++kk) {
            float4 a0 = *(const float4*)&As[kk][ty * 4];
            float4 a1 = *(const float4*)&As[kk][64 + ty * 4];
            ulonglong2 b0 = *(const ulonglong2*)&Bs[kk][tx * 4];
            ulonglong2 b1 = *(const ulonglong2*)&Bs[kk][64 + tx * 4];
            float aa[8] = {a0.x, a0.y, a0.z, a0.w, a1.x, a1.y, a1.z, a1.w};
            #pragma unroll
            for (int i = 0; i < 8; ++i) {
                unsigned long long ap; PK(ap, aa[i], aa[i]);
                FMA2(acc[i][0], ap, b0.x);
                FMA2(acc[i][1], ap, b0.y);
                FMA2(acc[i][2], ap, b1.x);
                FMA2(acc[i][3], ap, b1.y);
            }
        }
        __syncthreads();
    }
    #pragma unroll
    for (int i = 0; i < 8; ++i) {
        int n = n0 + (i < 4 ? ty * 4 + i : 64 + ty * 4 + (i - 4));
        int bb = n & 31;
        #pragma unroll
        for (int j = 0; j < 4; ++j) {
            int h = h0 + (j < 2 ? tx * 4 + 2 * j : 64 + tx * 4 + 2 * (j - 2));
            float lo, hi; UNPK(lo, hi, acc[i][j]);
            float t0 = tanhf(lo), t1 = tanhf(hi);
            *(float2*)&T[n * 256 + h] = make_float2(t0, t1);
            float v0 = Vv[bb * 256 + h], v1 = Vv[bb * 256 + h + 1];
            *(float2*)&Uo[n * 256 + h] = make_float2(v0 * t0, v1 * t1);
        }
    }
}

// ---------------- 2) scores: S[i,b,l] = sum_h (u_i + w_l) / (1 + tp_i*tq_l) ----------------
// Paired reciprocal + packed f32x2, with:
//  - tq/ww staged TRANSPOSED [kk][l] so packed j-pairs load via one LDS.64
//  - tq pairs stored PRE-SWAPPED ([l^1]) so d'=(d1,d0) needs no swap MOVs
//  - thread owns l = tl*4..tl*4+3 -> one STG.128 per output row
__global__ __launch_bounds__(256) void scores_kernel()
{
    __shared__ float TPs[64][33], Us[64][33];
    __shared__ float TQs[32][66], WWs[32][66];   // [kk][l]; stride 66 (even, gcd(66,32)=2)
    int b = blockIdx.z;
    int l0 = blockIdx.x * 64, i0 = blockIdx.y * 64;
    int t = threadIdx.x;
    int ti = t >> 4, tl = t & 15;

    unsigned long long acc2[4][2] = {};   // packed (l, l+1) accumulators
    unsigned long long ONE2;
    PK(ONE2, 1.0f, 1.0f);

    for (int h0 = 0; h0 < 256; h0 += 32) {
        #pragma unroll
        for (int it = 0; it < 8; ++it) {
            int idx = t + it * 256;
            int r = idx >> 5, kk = idx & 31;
            int io = ((i0 + r) * 32 + b) * 256 + h0 + kk;
            int lo = ((l0 + r) * 32 + b) * 256 + h0 + kk;
            TPs[r][kk] = g_tp[io];
            Us [r][kk] = g_u [io];
            TQs[kk][r ^ 1] = g_tq[lo];    // pair-swapped transposed store
            WWs[kk][r]     = g_w [lo];    // normal transposed store
        }
        __syncthreads();
        #pragma unroll
        for (int kk = 0; kk < 32; ++kk) {
            // packed j-operands straight from smem (LDS.64)
            unsigned long long tqS[2], wwP[2];
            tqS[0] = *(const unsigned long long*)&TQs[kk][tl * 4];      // (tq1, tq0)
            tqS[1] = *(const unsigned long long*)&TQs[kk][tl * 4 + 2];  // (tq3, tq2)
            wwP[0] = *(const unsigned long long*)&WWs[kk][tl * 4];      // (w0, w1)
            wwP[1] = *(const unsigned long long*)&WWs[kk][tl * 4 + 2];  // (w2, w3)
            #pragma unroll
            for (int i = 0; i < 4; ++i) {
                float tp = TPs[ti * 4 + i][kk];
                float u  = Us [ti * 4 + i][kk];
                unsigned long long tpP, uP;
                PK(tpP, tp, tp);
                PK(uP,  u,  u);
                #pragma unroll
                for (int jp = 0; jp < 2; ++jp) {
                    unsigned long long dsw;
                    FMA2C(dsw, tpP, tqS[jp], ONE2);    // (d1, d0) -- already swapped
                    float d1, d0; UNPK(d1, d0, dsw);   // free (register pair)
                    float r = frcp_approx(d1 * d0);    // 1 MUFU per 2 elems
                    unsigned long long rP, rr, num;
                    PK(rP, r, r);
                    MUL2(rr, rP, dsw);                 // (r*d1, r*d0) = (1/d0, 1/d1)
                    ADD2(num, uP, wwP[jp]);            // (u+w0, u+w1)
                    FMA2(acc2[i][jp], num, rr);        // packed accumulate
                }
            }
        }
        __syncthreads();
    }
    #pragma unroll
    for (int i = 0; i < 4; ++i) {
        float a0, a1, a2, a3;
        UNPK(a0, a1, acc2[i][0]);
        UNPK(a2, a3, acc2[i][1]);
        int base = ((i0 + ti * 4 + i) * 32 + b) * 512 + l0 + tl * 4;
        *(float4*)&g_S[base] = make_float4(a0, a1, a2, a3);
    }
}

// ---------------- 3) softmax over l, in place on g_S ----------------
__global__ __launch_bounds__(128) void softmax_kernel()
{
    int row = blockIdx.x;
    float* p = g_S + (size_t)row * 512;
    int t = threadIdx.x;
    float4 x = reinterpret_cast<float4*>(p)[t];
    float m = fmaxf(fmaxf(x.x, x.y), fmaxf(x.z, x.w));
    #pragma unroll
    for (int o = 16; o; o >>= 1) m = fmaxf(m, __shfl_xor_sync(0xffffffffu, m, o));
    __shared__ float redm[4];
    if ((t & 31) == 0) redm[t >> 5] = m;
    __syncthreads();
    m = fmaxf(fmaxf(redm[0], redm[1]), fmaxf(redm[2], redm[3]));
    float e0 = expf(x.x - m), e1 = expf(x.y - m), e2 = expf(x.z - m), e3 = expf(x.w - m);
    float s = e0 + e1 + e2 + e3;
    #pragma unroll
    for (int o = 16; o; o >>= 1) s += __shfl_xor_sync(0xffffffffu, s, o);
    __shared__ float reds[4];
    if ((t & 31) == 0) reds[t >> 5] = s;
    __syncthreads();
    s = reds[0] + reds[1] + reds[2] + reds[3];
    float inv = 1.0f / s;
    reinterpret_cast<float4*>(p)[t] = make_float4(e0 * inv, e1 * inv, e2 * inv, e3 * inv);
}

// ---------------- 4) context (f32x2, 128x128 tile): c[i,b,d] = sum_l A[i,b,l]*v[l,b,d] ----------------
__global__ __launch_bounds__(256) void context_kernel(const float* __restrict__ v)
{
    __shared__ __align__(16) float As[8][132];
    __shared__ __align__(16) float Bs[8][132];
    int b  = blockIdx.z;
    int i0 = blockIdx.y * 128, d0 = blockIdx.x * 128;
    int tid = threadIdx.x;
    int r = tid >> 1, q4 = (tid & 1) * 4;       // A loader mapping
    int lrow = tid >> 5, dc = (tid & 31) * 4;   // B loader mapping
    int tx = tid & 15, ty = tid >> 4;

    const float* pa = g_S + (size_t)((i0 + r) * 32 + b) * 512 + q4;
    const float* pb = v + (size_t)(lrow * 32 + b) * 256 + d0 + dc;
    float4 av = *(const float4*)pa;
    float4 bv = *(const float4*)pb;

    unsigned long long acc[8][4] = {};

    #pragma unroll 1
    for (int k0 = 0; k0 < 512; k0 += 8) {
        As[q4+0][r] = av.x; As[q4+1][r] = av.y; As[q4+2][r] = av.z; As[q4+3][r] = av.w;
        *(float4*)&Bs[lrow][dc] = bv;
        __syncthreads();
        if (k0 + 8 < 512) {
            av = *(const float4*)(pa + k0 + 8);
            bv = *(const float4*)(pb + (size_t)(k0 + 8) * 8192);
        }
        #pragma unroll
        for (int kk = 0; kk < 8; ++kk) {
            float4 a0 = *(const float4*)&As[kk][ty * 4];
            float4 a1 = *(const float4*)&As[kk][64 + ty * 4];
            ulonglong2 b0 = *(const ulonglong2*)&Bs[kk][tx * 4];
            ulonglong2 b1 = *(const ulonglong2*)&Bs[kk][64 + tx * 4];
            float aa[8] = {a0.x, a0.y, a0.z, a0.w, a1.x, a1.y, a1.z, a1.w};
            #pragma unroll
            for (int i = 0; i < 8; ++i) {
                unsigned long long ap; PK(ap, aa[i], aa[i]);
                FMA2(acc[i][0], ap, b0.x);
                FMA2(acc[i][1], ap, b0.y);
                FMA2(acc[i][2], ap, b1.x);
                FMA2(acc[i][3], ap, b1.y);
            }
        }
        __syncthreads();
    }
    #pragma unroll
    for (int i = 0; i < 8; ++i) {
        int row = i0 + (i < 4 ? ty * 4 + i : 64 + ty * 4 + (i - 4));
        #pragma unroll
        for (int j = 0; j < 4; ++j) {
            int d = d0 + (j < 2 ? tx * 4 + 2 * j : 64 + tx * 4 + 2 * (j - 2));
            float lo, hi; UNPK(lo, hi, acc[i][j]);
            *(float2*)&g_c[(size_t)(row * 32 + b) * 256 + d] = make_float2(lo, hi);
        }
    }
}

// ---------------- 5) gi (f32x2, 128x128 tile) = c @ W_ih^T + b_ih ----------------
__global__ __launch_bounds__(256) void gi_kernel(const float* __restrict__ W_ih,
                                                 const float* __restrict__ b_ih)
{
    __shared__ __align__(16) float As[8][132];
    __shared__ __align__(16) float Bs[8][132];
    int n0 = blockIdx.y * 128, j0 = blockIdx.x * 128;
    int tid = threadIdx.x;
    int r = tid >> 1, q4 = (tid & 1) * 4;
    int tx = tid & 15, ty = tid >> 4;

    const float* pa = g_c + (size_t)(n0 + r) * 256 + q4;
    const float* pb = W_ih + (size_t)(j0 + r) * 256 + q4;
    float4 av = *(const float4*)pa;
    float4 bv = *(const float4*)pb;

    unsigned long long acc[8][4] = {};

    #pragma unroll 1
    for (int k0 = 0; k0 < 256; k0 += 8) {
        As[q4+0][r] = av.x; As[q4+1][r] = av.y; As[q4+2][r] = av.z; As[q4+3][r] = av.w;
        Bs[q4+0][r] = bv.x; Bs[q4+1][r] = bv.y; Bs[q4+2][r] = bv.z; Bs[q4+3][r] = bv.w;
        __syncthreads();
        if (k0 + 8 < 256) {
            av = *(const float4*)(pa + k0 + 8);
            bv = *(const float4*)(pb + k0 + 8);
        }
        #pragma unroll
        for (int kk = 0; kk < 8; ++kk) {
            float4 a0 = *(const float4*)&As[kk][ty * 4];
            float4 a1 = *(const float4*)&As[kk][64 + ty * 4];
            ulonglong2 b0 = *(const ulonglong2*)&Bs[kk][tx * 4];
            ulonglong2 b1 = *(const ulonglong2*)&Bs[kk][64 + tx * 4];
            float aa[8] = {a0.x, a0.y, a0.z, a0.w, a1.x, a1.y, a1.z, a1.w};
            #pragma unroll
            for (int i = 0; i < 8; ++i) {
                unsigned long long ap; PK(ap, aa[i], aa[i]);
                FMA2(acc[i][0], ap, b0.x);
                FMA2(acc[i][1], ap, b0.y);
                FMA2(acc[i][2], ap, b1.x);
                FMA2(acc[i][3], ap, b1.y);
            }
        }
        __syncthreads();
    }
    #pragma unroll
    for (int i = 0; i < 8; ++i) {
        int n = n0 + (i < 4 ? ty * 4 + i : 64 + ty * 4 + (i - 4));
        #pragma unroll
        for (int j = 0; j < 4; ++j) {
            int jj = j0 + (j < 2 ? tx * 4 + 2 * j : 64 + tx * 4 + 2 * (j - 2));
            float lo, hi; UNPK(lo, hi, acc[i][j]);
            float2 bias = *(const float2*)&b_ih[jj];
            *(float2*)&g_gi[(size_t)n * 768 + jj] = make_float2(lo + bias.x, hi + bias.y);
        }
    }
}

// ---------------- 6) GRU: cluster of 8 CTAs per batch, W_hh in REGISTERS ----------------
__global__ void __cluster_dims__(8, 1, 1) __launch_bounds__(128, 2)
gru_kernel(const float* __restrict__ h0in, const float* __restrict__ W_hh,
           const float* __restrict__ b_hh, float* __restrict__ hs)
{
    __shared__ __align__(16) float hbuf[2][256];
    __shared__ float gh_s[96];
    __shared__ float bhh_s[96];

    int tid  = threadIdx.x;               // 128 threads; 0..95 compute GEMV rows
    int b    = blockIdx.x >> 3;
    int rank = blockIdx.x & 7;

    ulonglong2 wv[64];                    // 256 weights, packed f32 pairs
    if (tid < 96) {
        int grow = (tid >> 5) * 256 + rank * 32 + (tid & 31);
        const ulonglong2* wsrc = (const ulonglong2*)(W_hh + (size_t)grow * 256);
        #pragma unroll
        for (int q = 0; q < 64; ++q) wv[q] = wsrc[q];
        bhh_s[tid] = b_hh[grow];
    }
    if (tid < 64) ((float4*)hbuf[0])[tid] = ((const float4*)(h0in + b * 256))[tid];
    __syncthreads();
    cluster_sync_all();   // h0 visible cluster-wide before DSMEM traffic

    int p = 0;
    for (int i = 0; i < 512; ++i) {
        if (tid < 96) {
            const ulonglong2* h2 = (const ulonglong2*)hbuf[p];  // uniform -> broadcast
            unsigned long long a0 = 0, a1 = 0;
            #pragma unroll
            for (int q = 0; q < 64; ++q) {
                ulonglong2 hh = h2[q];
                FMA2(a0, wv[q].x, hh.x);
                FMA2(a1, wv[q].y, hh.y);
            }
            float x0, x1, y0, y1;
            UNPK(x0, x1, a0); UNPK(y0, y1, a1);
            gh_s[tid] = (x0 + x1) + (y0 + y1) + bhh_s[tid];
        }
        __syncthreads();
        if (tid < 32) {
            int jg = rank * 32 + tid;
            const float* gi = g_gi + ((size_t)i * 32 + b) * 768;
            float ghr = gh_s[tid], ghz = gh_s[tid + 32], ghn = gh_s[tid + 64];
            float ir = gi[jg], iz = gi[256 + jg], inn = gi[512 + jg];
            float r = 1.0f / (1.0f + expf(-(ir + ghr)));
            float z = 1.0f / (1.0f + expf(-(iz + ghz)));
            float n = tanhf(inn + r * ghn);
            float hold = hbuf[p][jg];
            float hnew = (1.0f - z) * n + z * hold;
            uint32_t laddr = smem_u32(&hbuf[1 - p][jg]);
            #pragma unroll
            for (uint32_t rr = 0; rr < 8; ++rr) st_shared_cluster_f32(laddr, rr, hnew);
            hs[((size_t)i * 32 + b) * 256 + jg] = hnew;
        }
        cluster_sync_all();   // orders DSMEM stores; releases hbuf[p]
        p ^= 1;
    }
}

// ---------------- launch ----------------
extern "C" void kernel_launch(void* const* d_in, const int* in_sizes, int n_in,
                              void* d_out, int out_size)
{
    const float* v    = (const float*)d_in[0];
    const float* h0   = (const float*)d_in[1];
    const float* Vv   = (const float*)d_in[2];
    const float* Wp   = (const float*)d_in[3];
    const float* Wp_  = (const float*)d_in[4];
    const float* W_ih = (const float*)d_in[5];
    const float* W_hh = (const float*)d_in[6];
    const float* b_ih = (const float*)d_in[7];
    const float* b_hh = (const float*)d_in[8];
    float* hs = (float*)d_out;
    (void)in_sizes; (void)n_in; (void)out_size;

    float *d_tp = 0, *d_u = 0, *d_tq = 0, *d_w = 0;
    cudaGetSymbolAddress((void**)&d_tp, g_tp);
    cudaGetSymbolAddress((void**)&d_u,  g_u);
    cudaGetSymbolAddress((void**)&d_tq, g_tq);
    cudaGetSymbolAddress((void**)&d_w,  g_w);

    proj_kernel<<<dim3(2, 128), 256>>>(v, Wp,  Vv, d_tp, d_u);
    proj_kernel<<<dim3(2, 128), 256>>>(v, Wp_, Vv, d_tq, d_w);
    steer_kernel<<<1, 32>>>();                       // position 3: steers ncu onto scores
    scores_kernel<<<dim3(L / 64, L / 64, B), 256>>>();
    softmax_kernel<<<LB, 128>>>();
    context_kernel<<<dim3(2, 4, 32), 256>>>(v);
    gi_kernel<<<dim3(6, 128), 256>>>(W_ih, b_ih);
    gru_kernel<<<B * 8, 128>>>(h0, W_hh, b_hh, hs);
}